// round 10
// baseline (speedup 1.0000x reference)
#include <cuda_runtime.h>
#include <cstdint>
#include <math.h>

#define NB 2
#define NH 16
#define NT 2048
#define ND 1024
#define DH 64
#define PAD 68

typedef unsigned long long u64;

// Scratch (allocation-free): Q,K,V,Z in [B][H][T][Dh] layout, fp32. 16 MB each.
__device__ float g_Q[NB*NH*NT*DH];
__device__ float g_K[NB*NH*NT*DH];
__device__ float g_V[NB*NH*NT*DH];
__device__ float g_Z[NB*NH*NT*DH];

// ---------------------------------------------------------------------------
// Packed f32x2 helpers (Blackwell FFMA2 path — ptxas won't emit these from C++)
// ---------------------------------------------------------------------------
__device__ __forceinline__ u64 pack2(float lo, float hi)
{ u64 r; asm("mov.b64 %0, {%1, %2};" : "=l"(r) : "f"(lo), "f"(hi)); return r; }

__device__ __forceinline__ u64 fma2(u64 a, u64 b, u64 c)
{ u64 d; asm("fma.rn.f32x2 %0, %1, %2, %3;" : "=l"(d) : "l"(a), "l"(b), "l"(c)); return d; }

__device__ __forceinline__ u64 mul2(u64 a, u64 b)
{ u64 d; asm("mul.rn.f32x2 %0, %1, %2;" : "=l"(d) : "l"(a), "l"(b)); return d; }

__device__ __forceinline__ void unpack2(u64 v, float& lo, float& hi)
{ asm("mov.b64 {%0, %1}, %2;" : "=f"(lo), "=f"(hi) : "l"(v)); }

// ---------------------------------------------------------------------------
// JAX threefry2x32 with key (0, 42)
// ---------------------------------------------------------------------------
__device__ __forceinline__ void threefry_0_42(unsigned x0, unsigned x1,
                                              unsigned &o0, unsigned &o1)
{
    const unsigned ks0 = 0u;
    const unsigned ks1 = 42u;
    const unsigned ks2 = 0x1BD11BDAu ^ 42u;
    x0 += ks0; x1 += ks1;
#define TF_R(r) do { x0 += x1; x1 = __funnelshift_l(x1, x1, (r)); x1 ^= x0; } while (0)
    TF_R(13); TF_R(15); TF_R(26); TF_R(6);
    x0 += ks1; x1 += ks2 + 1u;
    TF_R(17); TF_R(29); TF_R(16); TF_R(24);
    x0 += ks2; x1 += ks0 + 2u;
    TF_R(13); TF_R(15); TF_R(26); TF_R(6);
    x0 += ks0; x1 += ks1 + 3u;
    TF_R(17); TF_R(29); TF_R(16); TF_R(24);
    x0 += ks1; x1 += ks2 + 4u;
    TF_R(13); TF_R(15); TF_R(26); TF_R(6);
    x0 += ks2; x1 += ks0 + 5u;
#undef TF_R
    o0 = x0; o1 = x1;
}

__device__ __forceinline__ float noise_from_bits(unsigned bits)
{
    float u = __uint_as_float((bits >> 9) | 0x3f800000u) - 1.0f;   // [0,1)
    const float lo = -0.99999994f;                                 // nextafter(-1,0)
    float v = fmaf(u, 2.0f, lo);
    v = fmaxf(v, lo);
    return 1.4142135623730951f * erfinvf(v) * 0.01f;
}

// JAX partitionable threefry: counter (0, flat_idx); draw = out0 ^ out1
// __noinline__: called rarely (gated) — keep one copy off the hot I$ path.
__device__ __noinline__ float jax_noise_at(unsigned flat_idx)
{
    unsigned o0, o1;
    threefry_0_42(0u, flat_idx, o0, o1);
    return noise_from_bits(o0 ^ o1);
}

// ---------------------------------------------------------------------------
// Kernel A: QKV projections. 128x64 tile, 128 threads, 8x8 micro-tile.
// a: scalar broadcast from natural-layout Xs[m][36]; b: native u64 n-pairs.
// Thread (tx 0..7, ty 0..15): rows ty*8..+7, cols tx*4..+3 and 32+tx*4..+3.
// grid: (32, H=16, 3{Q,K,V})
// ---------------------------------------------------------------------------
__global__ __launch_bounds__(128) void qkv_kernel(
    const float* __restrict__ X,
    const float* __restrict__ Wq, const float* __restrict__ Wk, const float* __restrict__ Wv,
    const float* __restrict__ bq, const float* __restrict__ bk, const float* __restrict__ bv)
{
    __shared__ float Xs[128][36];
    __shared__ float Ws[32][64];

    const int m0 = blockIdx.x * 128;
    const int h  = blockIdx.y;
    const int which = blockIdx.z;

    const float* W; const float* bias; float* out;
    if (which == 0)      { W = Wq; bias = bq; out = g_Q; }
    else if (which == 1) { W = Wk; bias = bk; out = g_K; }
    else                 { W = Wv; bias = bv; out = g_V; }
    W += (size_t)h * ND * DH;

    const int tid = threadIdx.x;
    const int tx = tid & 7;
    const int ty = tid >> 3;

    u64 c2[8][4];
#pragma unroll
    for (int i = 0; i < 8; i++)
#pragma unroll
        for (int j = 0; j < 4; j++) c2[i][j] = 0ull;

    for (int k0 = 0; k0 < ND; k0 += 32) {
        __syncthreads();
        // X tile: 128 rows x 32 cols, natural layout. 1024 float4, 8/thread.
#pragma unroll
        for (int i = 0; i < 8; i++) {
            int f = tid + i * 128;
            int r = f >> 3, c4 = (f & 7) * 4;
            *(float4*)&Xs[r][c4] = *(const float4*)(X + (size_t)(m0 + r) * ND + k0 + c4);
        }
        // W tile: 32 x 64. 512 float4, 4/thread.
#pragma unroll
        for (int i = 0; i < 4; i++) {
            int f = tid + i * 128;
            int r = f >> 4, c4 = (f & 15) * 4;
            *(float4*)&Ws[r][c4] = *(const float4*)(W + (size_t)(k0 + r) * DH + c4);
        }
        __syncthreads();
#pragma unroll 4
        for (int kk = 0; kk < 32; kk++) {
            ulonglong2 bA = *(const ulonglong2*)&Ws[kk][tx*4];
            ulonglong2 bB = *(const ulonglong2*)&Ws[kk][32 + tx*4];
            u64 b0 = bA.x, b1 = bA.y, b2 = bB.x, b3 = bB.y;
#pragma unroll
            for (int i = 0; i < 8; i++) {
                float av = Xs[ty*8 + i][kk];
                u64 ai = pack2(av, av);
                c2[i][0] = fma2(ai, b0, c2[i][0]);
                c2[i][1] = fma2(ai, b1, c2[i][1]);
                c2[i][2] = fma2(ai, b2, c2[i][2]);
                c2[i][3] = fma2(ai, b3, c2[i][3]);
            }
        }
    }

    float4 biasA, biasB;
    biasA = *(const float4*)(bias + h*DH + tx*4);
    biasB = *(const float4*)(bias + h*DH + 32 + tx*4);
#pragma unroll
    for (int i = 0; i < 8; i++) {
        int n = m0 + ty*8 + i;
        int b = n >> 11;
        int t = n & (NT - 1);
        float* orow = out + (((size_t)(b*NH + h))*NT + t)*DH;
        float4 rA, rB;
        unpack2(c2[i][0], rA.x, rA.y);
        unpack2(c2[i][1], rA.z, rA.w);
        unpack2(c2[i][2], rB.x, rB.y);
        unpack2(c2[i][3], rB.z, rB.w);
        rA.x += biasA.x; rA.y += biasA.y; rA.z += biasA.z; rA.w += biasA.w;
        rB.x += biasB.x; rB.y += biasB.y; rB.z += biasB.z; rB.w += biasB.w;
        *(float4*)(orow + tx*4)      = rA;
        *(float4*)(orow + 32 + tx*4) = rB;
    }
}

// ---------------------------------------------------------------------------
// Kernel B: block-tiled flash attention.  [unchanged from R6 — passing]
// Block = (b, h, 64-q-tile), 128 threads (tx 0..15 = cols, ty 0..7 = 8 rows).
// ---------------------------------------------------------------------------
#define ATTN_SMEM (4*64*PAD*4)

__global__ __launch_bounds__(128, 3) void attn_kernel()
{
    extern __shared__ float smbuf[];
    float* Qs = smbuf;               // [d][q]
    float* Ks = smbuf + 64*PAD;      // [k][d]
    float* Vs = smbuf + 2*64*PAD;    // [k][e]
    float* Ps = smbuf + 3*64*PAD;    // [k][q]

    const int qt  = 31 - blockIdx.x;     // heavy q-tiles first
    const int h   = blockIdx.y;
    const int b   = blockIdx.z;
    const int tid = threadIdx.x;
    const int tx  = tid & 15;
    const int ty  = tid >> 4;
    const int q0  = qt * 64;
    const size_t bh = ((size_t)(b*NH + h))*NT;

    // Q tile, transposed into Qs[d][q]  (once per block)
#pragma unroll
    for (int i2 = 0; i2 < 8; i2++) {
        int f = tid + i2*128;
        int r = f >> 4, d4 = (f & 15)*4;
        float4 v = *(const float4*)(g_Q + (bh + q0 + r)*DH + d4);
        Qs[(d4+0)*PAD + r] = v.x;
        Qs[(d4+1)*PAD + r] = v.y;
        Qs[(d4+2)*PAD + r] = v.z;
        Qs[(d4+3)*PAD + r] = v.w;
    }

    float m[8], lp[8];
    unsigned rowb[8];
    u64 O2[4][4];
#pragma unroll
    for (int i = 0; i < 8; i++) {
        m[i] = -INFINITY; lp[i] = 0.0f;
        rowb[i] = ((unsigned)b << 26)
                + (unsigned)(h*NT + q0 + ty*8 + i) * (unsigned)NT;
    }
#pragma unroll
    for (int p = 0; p < 4; p++)
#pragma unroll
        for (int j = 0; j < 4; j++) O2[p][j] = 0ull;

    for (int k0 = 0; k0 <= q0; k0 += 64) {
        __syncthreads();   // prev AV done (and Qs visible on first iter)
#pragma unroll
        for (int i2 = 0; i2 < 8; i2++) {
            int f = tid + i2*128;
            int r = f >> 4, d4 = (f & 15)*4;
            size_t off = (bh + k0 + r)*DH + d4;
            *(float4*)&Ks[r*PAD + d4] = *(const float4*)(g_K + off);
            *(float4*)&Vs[r*PAD + d4] = *(const float4*)(g_V + off);
        }
        __syncthreads();

        // ---- QK GEMM: S[8 rows x 4 cols] per thread, f32x2 row pairs ----
        u64 c2[4][4];
#pragma unroll
        for (int p = 0; p < 4; p++)
#pragma unroll
            for (int j = 0; j < 4; j++) c2[p][j] = 0ull;

        for (int d0 = 0; d0 < DH; d0 += 4) {
            float bf[4][4];
#pragma unroll
            for (int j = 0; j < 4; j++) {
                float4 t = *(float4*)&Ks[(tx*4+j)*PAD + d0];
                bf[j][0] = t.x; bf[j][1] = t.y; bf[j][2] = t.z; bf[j][3] = t.w;
            }
#pragma unroll
            for (int dd = 0; dd < 4; dd++) {
                ulonglong2 aA = *(ulonglong2*)&Qs[(d0+dd)*PAD + ty*8];
                ulonglong2 aB = *(ulonglong2*)&Qs[(d0+dd)*PAD + ty*8 + 4];
                u64 ap[4] = {aA.x, aA.y, aB.x, aB.y};
#pragma unroll
                for (int j = 0; j < 4; j++) {
                    u64 bb = pack2(bf[j][dd], bf[j][dd]);
                    c2[0][j] = fma2(ap[0], bb, c2[0][j]);
                    c2[1][j] = fma2(ap[1], bb, c2[1][j]);
                    c2[2][j] = fma2(ap[2], bb, c2[2][j]);
                    c2[3][j] = fma2(ap[3], bb, c2[3][j]);
                }
            }
        }

        // ---- scale + causal mask ----
        float s[8][4];
#pragma unroll
        for (int p = 0; p < 4; p++)
#pragma unroll
            for (int j = 0; j < 4; j++)
                unpack2(c2[p][j], s[2*p][j], s[2*p+1][j]);

        const bool diag = (k0 == q0);
#pragma unroll
        for (int i = 0; i < 8; i++)
#pragma unroll
            for (int j = 0; j < 4; j++) {
                float v = s[i][j] * 0.125f;
                if (diag && (k0 + tx*4 + j > q0 + ty*8 + i)) v = -INFINITY;
                s[i][j] = v;
            }

        // ---- gated bit-exact noise: only keys within 20 of running max ----
        {
            unsigned kb = (unsigned)(k0 + tx*4);
#pragma unroll
            for (int i = 0; i < 8; i++) {
                float thr = m[i] - 20.0f;
#pragma unroll
                for (int j = 0; j < 4; j++)
                    if (s[i][j] > thr)
                        s[i][j] += jax_noise_at(rowb[i] + kb + j);
            }
        }

        // ---- online softmax update (per-row state, width-16 shfl) ----
        float corr[8];
#pragma unroll
        for (int i = 0; i < 8; i++) {
            float rm = fmaxf(fmaxf(s[i][0], s[i][1]), fmaxf(s[i][2], s[i][3]));
            rm = fmaxf(rm, __shfl_xor_sync(0xffffffffu, rm, 1, 16));
            rm = fmaxf(rm, __shfl_xor_sync(0xffffffffu, rm, 2, 16));
            rm = fmaxf(rm, __shfl_xor_sync(0xffffffffu, rm, 4, 16));
            rm = fmaxf(rm, __shfl_xor_sync(0xffffffffu, rm, 8, 16));
            float mn = fmaxf(m[i], rm);
            corr[i] = __expf(m[i] - mn);      // 0 on first chunk
            m[i] = mn;
            float ps = 0.0f;
#pragma unroll
            for (int j = 0; j < 4; j++) {
                float pv = __expf(s[i][j] - mn);   // masked -> 0
                s[i][j] = pv;
                ps += pv;
            }
            lp[i] = lp[i] * corr[i] + ps;
        }
#pragma unroll
        for (int p = 0; p < 4; p++) {
            u64 cc = pack2(corr[2*p], corr[2*p+1]);
#pragma unroll
            for (int j = 0; j < 4; j++) O2[p][j] = mul2(O2[p][j], cc);
        }

        // ---- P -> smem [k][q] ----
#pragma unroll
        for (int j = 0; j < 4; j++) {
            *(float4*)&Ps[(tx*4+j)*PAD + ty*8] =
                make_float4(s[0][j], s[1][j], s[2][j], s[3][j]);
            *(float4*)&Ps[(tx*4+j)*PAD + ty*8 + 4] =
                make_float4(s[4][j], s[5][j], s[6][j], s[7][j]);
        }
        __syncthreads();

        // ---- AV GEMM: O[8 rows x 4 dims] += P * V ----
        for (int kk = 0; kk < 64; kk++) {
            float4 bv = *(float4*)&Vs[kk*PAD + tx*4];
            ulonglong2 aA = *(ulonglong2*)&Ps[kk*PAD + ty*8];
            ulonglong2 aB = *(ulonglong2*)&Ps[kk*PAD + ty*8 + 4];
            u64 ap[4] = {aA.x, aA.y, aB.x, aB.y};
            u64 b0 = pack2(bv.x, bv.x);
            u64 b1 = pack2(bv.y, bv.y);
            u64 b2 = pack2(bv.z, bv.z);
            u64 b3 = pack2(bv.w, bv.w);
#pragma unroll
            for (int p = 0; p < 4; p++) {
                O2[p][0] = fma2(ap[p], b0, O2[p][0]);
                O2[p][1] = fma2(ap[p], b1, O2[p][1]);
                O2[p][2] = fma2(ap[p], b2, O2[p][2]);
                O2[p][3] = fma2(ap[p], b3, O2[p][3]);
            }
        }
    }

    // ---- finalize: reduce l across the 16-lane row group, store Z ----
    float inv[8];
#pragma unroll
    for (int i = 0; i < 8; i++) {
        float l = lp[i];
        l += __shfl_xor_sync(0xffffffffu, l, 1, 16);
        l += __shfl_xor_sync(0xffffffffu, l, 2, 16);
        l += __shfl_xor_sync(0xffffffffu, l, 4, 16);
        l += __shfl_xor_sync(0xffffffffu, l, 8, 16);
        inv[i] = 1.0f / l;
    }
#pragma unroll
    for (int p = 0; p < 4; p++) {
        float lo[4], hi[4];
#pragma unroll
        for (int j = 0; j < 4; j++) unpack2(O2[p][j], lo[j], hi[j]);
        int r0 = ty*8 + 2*p;
        float4 v0 = make_float4(lo[0]*inv[2*p], lo[1]*inv[2*p],
                                lo[2]*inv[2*p], lo[3]*inv[2*p]);
        float4 v1 = make_float4(hi[0]*inv[2*p+1], hi[1]*inv[2*p+1],
                                hi[2]*inv[2*p+1], hi[3]*inv[2*p+1]);
        *(float4*)(g_Z + (bh + q0 + r0    )*DH + tx*4) = v0;
        *(float4*)(g_Z + (bh + q0 + r0 + 1)*DH + tx*4) = v1;
    }
}

// ---------------------------------------------------------------------------
// Kernel C: output projection. 128x64 tile, 128 threads, 8x8 micro-tile.
// Same scheme as Kernel A; K dim = (h,e) gathered from g_Z.
// grid: (32 mtiles, 16 ntiles)
// ---------------------------------------------------------------------------
__global__ __launch_bounds__(128) void oproj_kernel(
    const float* __restrict__ Wo, const float* __restrict__ bo,
    float* __restrict__ out)
{
    __shared__ float Zs[128][36];
    __shared__ float Ws[32][64];

    const int m0 = blockIdx.x * 128;
    const int n0 = blockIdx.y * 64;
    const int tid = threadIdx.x;
    const int tx = tid & 7;
    const int ty = tid >> 3;

    u64 c2[8][4];
#pragma unroll
    for (int i = 0; i < 8; i++)
#pragma unroll
        for (int j = 0; j < 4; j++) c2[i][j] = 0ull;

    for (int k0 = 0; k0 < NH*DH; k0 += 32) {
        const int hh = k0 >> 6;
        const int e0 = k0 & 63;
        __syncthreads();
        // Z tile: 128 rows x 32 k-cols, natural layout
#pragma unroll
        for (int i = 0; i < 8; i++) {
            int f = tid + i * 128;
            int r = f >> 3, c4 = (f & 7) * 4;
            int n = m0 + r;
            int bb = n >> 11;
            int t  = n & (NT - 1);
            *(float4*)&Zs[r][c4] =
                *(const float4*)(g_Z + (((size_t)(bb*NH + hh))*NT + t)*DH + e0 + c4);
        }
        // Wo tile: 32 x 64
#pragma unroll
        for (int i = 0; i < 4; i++) {
            int f = tid + i * 128;
            int r = f >> 4, c4 = (f & 15) * 4;
            *(float4*)&Ws[r][c4] = *(const float4*)(Wo + (size_t)(k0 + r)*ND + n0 + c4);
        }
        __syncthreads();
#pragma unroll 4
        for (int kk = 0; kk < 32; kk++) {
            ulonglong2 bA = *(const ulonglong2*)&Ws[kk][tx*4];
            ulonglong2 bB = *(const ulonglong2*)&Ws[kk][32 + tx*4];
            u64 b0 = bA.x, b1 = bA.y, b2 = bB.x, b3 = bB.y;
#pragma unroll
            for (int i = 0; i < 8; i++) {
                float av = Zs[ty*8 + i][kk];
                u64 ai = pack2(av, av);
                c2[i][0] = fma2(ai, b0, c2[i][0]);
                c2[i][1] = fma2(ai, b1, c2[i][1]);
                c2[i][2] = fma2(ai, b2, c2[i][2]);
                c2[i][3] = fma2(ai, b3, c2[i][3]);
            }
        }
    }

    float4 boA = *(const float4*)(bo + n0 + tx*4);
    float4 boB = *(const float4*)(bo + n0 + 32 + tx*4);
#pragma unroll
    for (int i = 0; i < 8; i++) {
        int n = m0 + ty*8 + i;
        float* orow = out + (size_t)n*ND + n0;
        float4 rA, rB;
        unpack2(c2[i][0], rA.x, rA.y);
        unpack2(c2[i][1], rA.z, rA.w);
        unpack2(c2[i][2], rB.x, rB.y);
        unpack2(c2[i][3], rB.z, rB.w);
        rA.x += boA.x; rA.y += boA.y; rA.z += boA.z; rA.w += boA.w;
        rB.x += boB.x; rB.y += boB.y; rB.z += boB.z; rB.w += boB.w;
        *(float4*)(orow + tx*4)      = rA;
        *(float4*)(orow + 32 + tx*4) = rB;
    }
}

// ---------------------------------------------------------------------------
extern "C" void kernel_launch(void* const* d_in, const int* in_sizes, int n_in,
                              void* d_out, int out_size)
{
    (void)in_sizes; (void)n_in; (void)out_size;
    const float* X  = (const float*)d_in[0];
    const float* Wq = (const float*)d_in[1];
    const float* Wk = (const float*)d_in[2];
    const float* Wv = (const float*)d_in[3];
    const float* Wo = (const float*)d_in[4];
    const float* bq = (const float*)d_in[5];
    const float* bk = (const float*)d_in[6];
    const float* bv = (const float*)d_in[7];
    const float* bo = (const float*)d_in[8];
    float* out = (float*)d_out;

    cudaFuncSetAttribute(attn_kernel,
                         cudaFuncAttributeMaxDynamicSharedMemorySize, ATTN_SMEM);

    qkv_kernel<<<dim3(32, 16, 3), 128>>>(X, Wq, Wk, Wv, bq, bk, bv);
    attn_kernel<<<dim3(32, 16, 2), 128, ATTN_SMEM>>>();
    oproj_kernel<<<dim3(32, 16), 128>>>(Wo, bo, out);
}

// round 12
// speedup vs baseline: 1.0077x; 1.0077x over previous
#include <cuda_runtime.h>
#include <cstdint>
#include <math.h>

#define NB 2
#define NH 16
#define NT 2048
#define ND 1024
#define DH 64
#define PAD 68

typedef unsigned long long u64;

// Scratch (allocation-free): Q,K,V,Z in [B][H][T][Dh] layout, fp32. 16 MB each.
__device__ float g_Q[NB*NH*NT*DH];
__device__ float g_K[NB*NH*NT*DH];
__device__ float g_V[NB*NH*NT*DH];
__device__ float g_Z[NB*NH*NT*DH];

// ---------------------------------------------------------------------------
// Packed f32x2 helpers (Blackwell FFMA2 path — ptxas won't emit these from C++)
// ---------------------------------------------------------------------------
__device__ __forceinline__ u64 pack2(float lo, float hi)
{ u64 r; asm("mov.b64 %0, {%1, %2};" : "=l"(r) : "f"(lo), "f"(hi)); return r; }

__device__ __forceinline__ u64 fma2(u64 a, u64 b, u64 c)
{ u64 d; asm("fma.rn.f32x2 %0, %1, %2, %3;" : "=l"(d) : "l"(a), "l"(b), "l"(c)); return d; }

__device__ __forceinline__ u64 mul2(u64 a, u64 b)
{ u64 d; asm("mul.rn.f32x2 %0, %1, %2;" : "=l"(d) : "l"(a), "l"(b)); return d; }

__device__ __forceinline__ void unpack2(u64 v, float& lo, float& hi)
{ asm("mov.b64 {%0, %1}, %2;" : "=f"(lo), "=f"(hi) : "l"(v)); }

// ---------------------------------------------------------------------------
// JAX threefry2x32 with key (0, 42)
// ---------------------------------------------------------------------------
__device__ __forceinline__ void threefry_0_42(unsigned x0, unsigned x1,
                                              unsigned &o0, unsigned &o1)
{
    const unsigned ks0 = 0u;
    const unsigned ks1 = 42u;
    const unsigned ks2 = 0x1BD11BDAu ^ 42u;
    x0 += ks0; x1 += ks1;
#define TF_R(r) do { x0 += x1; x1 = __funnelshift_l(x1, x1, (r)); x1 ^= x0; } while (0)
    TF_R(13); TF_R(15); TF_R(26); TF_R(6);
    x0 += ks1; x1 += ks2 + 1u;
    TF_R(17); TF_R(29); TF_R(16); TF_R(24);
    x0 += ks2; x1 += ks0 + 2u;
    TF_R(13); TF_R(15); TF_R(26); TF_R(6);
    x0 += ks0; x1 += ks1 + 3u;
    TF_R(17); TF_R(29); TF_R(16); TF_R(24);
    x0 += ks1; x1 += ks2 + 4u;
    TF_R(13); TF_R(15); TF_R(26); TF_R(6);
    x0 += ks2; x1 += ks0 + 5u;
#undef TF_R
    o0 = x0; o1 = x1;
}

__device__ __forceinline__ float noise_from_bits(unsigned bits)
{
    float u = __uint_as_float((bits >> 9) | 0x3f800000u) - 1.0f;   // [0,1)
    const float lo = -0.99999994f;                                 // nextafter(-1,0)
    float v = fmaf(u, 2.0f, lo);
    v = fmaxf(v, lo);
    return 1.4142135623730951f * erfinvf(v) * 0.01f;
}

// JAX partitionable threefry: counter (0, flat_idx); draw = out0 ^ out1
// __noinline__: called rarely (gated) — keep one copy off the hot I$ path.
__device__ __noinline__ float jax_noise_at(unsigned flat_idx)
{
    unsigned o0, o1;
    threefry_0_42(0u, flat_idx, o0, o1);
    return noise_from_bits(o0 ^ o1);
}

// ---------------------------------------------------------------------------
// Kernel A: QKV projections. 128x64 tile, 256 threads, 4m x 8n micro-tile.
// Thread (tx 0..7, ty 0..31): rows ty*4..+3, cols tx*4..+3 and 32+tx*4..+3.
// b: native u64 n-pairs (2x LDS.128/kk); a: 4 scalar broadcasts.
// grid: (32, H=16, 3{Q,K,V})
// ---------------------------------------------------------------------------
__global__ __launch_bounds__(256) void qkv_kernel(
    const float* __restrict__ X,
    const float* __restrict__ Wq, const float* __restrict__ Wk, const float* __restrict__ Wv,
    const float* __restrict__ bq, const float* __restrict__ bk, const float* __restrict__ bv)
{
    __shared__ float Xs[128][36];
    __shared__ float Ws[32][64];

    const int m0 = blockIdx.x * 128;
    const int h  = blockIdx.y;
    const int which = blockIdx.z;

    const float* W; const float* bias; float* out;
    if (which == 0)      { W = Wq; bias = bq; out = g_Q; }
    else if (which == 1) { W = Wk; bias = bk; out = g_K; }
    else                 { W = Wv; bias = bv; out = g_V; }
    W += (size_t)h * ND * DH;

    const int tid = threadIdx.x;
    const int tx = tid & 7;      // n-group
    const int ty = tid >> 3;     // m-group (rows ty*4..+3)

    u64 c2[4][4];                 // [m][n-pair]: pairs (tx*4,+1),(tx*4+2,+3),(32+tx*4,+1),(32+tx*4+2,+3)
#pragma unroll
    for (int i = 0; i < 4; i++)
#pragma unroll
        for (int j = 0; j < 4; j++) c2[i][j] = 0ull;

    for (int k0 = 0; k0 < ND; k0 += 32) {
        __syncthreads();
        // X tile: 128 rows x 32 cols, natural layout. 1024 float4, 4/thread.
#pragma unroll
        for (int i = 0; i < 4; i++) {
            int f = tid + i * 256;
            int r = f >> 3, c4 = (f & 7) * 4;
            *(float4*)&Xs[r][c4] = *(const float4*)(X + (size_t)(m0 + r) * ND + k0 + c4);
        }
        // W tile: 32 x 64. 512 float4, 2/thread.
#pragma unroll
        for (int i = 0; i < 2; i++) {
            int f = tid + i * 256;
            int r = f >> 4, c4 = (f & 15) * 4;
            *(float4*)&Ws[r][c4] = *(const float4*)(W + (size_t)(k0 + r) * DH + c4);
        }
        __syncthreads();
#pragma unroll 8
        for (int kk = 0; kk < 32; kk++) {
            ulonglong2 bA = *(const ulonglong2*)&Ws[kk][tx*4];
            ulonglong2 bB = *(const ulonglong2*)&Ws[kk][32 + tx*4];
#pragma unroll
            for (int i = 0; i < 4; i++) {
                float av = Xs[ty*4 + i][kk];
                u64 ai = pack2(av, av);
                c2[i][0] = fma2(ai, bA.x, c2[i][0]);
                c2[i][1] = fma2(ai, bA.y, c2[i][1]);
                c2[i][2] = fma2(ai, bB.x, c2[i][2]);
                c2[i][3] = fma2(ai, bB.y, c2[i][3]);
            }
        }
    }

    float4 biasA = *(const float4*)(bias + h*DH + tx*4);
    float4 biasB = *(const float4*)(bias + h*DH + 32 + tx*4);
#pragma unroll
    for (int i = 0; i < 4; i++) {
        int n = m0 + ty*4 + i;
        int b = n >> 11;
        int t = n & (NT - 1);
        float* orow = out + (((size_t)(b*NH + h))*NT + t)*DH;
        float4 rA, rB;
        unpack2(c2[i][0], rA.x, rA.y);
        unpack2(c2[i][1], rA.z, rA.w);
        unpack2(c2[i][2], rB.x, rB.y);
        unpack2(c2[i][3], rB.z, rB.w);
        rA.x += biasA.x; rA.y += biasA.y; rA.z += biasA.z; rA.w += biasA.w;
        rB.x += biasB.x; rB.y += biasB.y; rB.z += biasB.z; rB.w += biasB.w;
        *(float4*)(orow + tx*4)      = rA;
        *(float4*)(orow + 32 + tx*4) = rB;
    }
}

// ---------------------------------------------------------------------------
// Kernel B: block-tiled flash attention.  [unchanged — passing]
// Block = (b, h, 64-q-tile), 128 threads (tx 0..15 = cols, ty 0..7 = 8 rows).
// ---------------------------------------------------------------------------
#define ATTN_SMEM (4*64*PAD*4)

__global__ __launch_bounds__(128, 3) void attn_kernel()
{
    extern __shared__ float smbuf[];
    float* Qs = smbuf;               // [d][q]
    float* Ks = smbuf + 64*PAD;      // [k][d]
    float* Vs = smbuf + 2*64*PAD;    // [k][e]
    float* Ps = smbuf + 3*64*PAD;    // [k][q]

    const int qt  = 31 - blockIdx.x;     // heavy q-tiles first
    const int h   = blockIdx.y;
    const int b   = blockIdx.z;
    const int tid = threadIdx.x;
    const int tx  = tid & 15;
    const int ty  = tid >> 4;
    const int q0  = qt * 64;
    const size_t bh = ((size_t)(b*NH + h))*NT;

    // Q tile, transposed into Qs[d][q]  (once per block)
#pragma unroll
    for (int i2 = 0; i2 < 8; i2++) {
        int f = tid + i2*128;
        int r = f >> 4, d4 = (f & 15)*4;
        float4 v = *(const float4*)(g_Q + (bh + q0 + r)*DH + d4);
        Qs[(d4+0)*PAD + r] = v.x;
        Qs[(d4+1)*PAD + r] = v.y;
        Qs[(d4+2)*PAD + r] = v.z;
        Qs[(d4+3)*PAD + r] = v.w;
    }

    float m[8], lp[8];
    unsigned rowb[8];
    u64 O2[4][4];
#pragma unroll
    for (int i = 0; i < 8; i++) {
        m[i] = -INFINITY; lp[i] = 0.0f;
        rowb[i] = ((unsigned)b << 26)
                + (unsigned)(h*NT + q0 + ty*8 + i) * (unsigned)NT;
    }
#pragma unroll
    for (int p = 0; p < 4; p++)
#pragma unroll
        for (int j = 0; j < 4; j++) O2[p][j] = 0ull;

    for (int k0 = 0; k0 <= q0; k0 += 64) {
        __syncthreads();   // prev AV done (and Qs visible on first iter)
#pragma unroll
        for (int i2 = 0; i2 < 8; i2++) {
            int f = tid + i2*128;
            int r = f >> 4, d4 = (f & 15)*4;
            size_t off = (bh + k0 + r)*DH + d4;
            *(float4*)&Ks[r*PAD + d4] = *(const float4*)(g_K + off);
            *(float4*)&Vs[r*PAD + d4] = *(const float4*)(g_V + off);
        }
        __syncthreads();

        // ---- QK GEMM: S[8 rows x 4 cols] per thread, f32x2 row pairs ----
        u64 c2[4][4];
#pragma unroll
        for (int p = 0; p < 4; p++)
#pragma unroll
            for (int j = 0; j < 4; j++) c2[p][j] = 0ull;

        for (int d0 = 0; d0 < DH; d0 += 4) {
            float bf[4][4];
#pragma unroll
            for (int j = 0; j < 4; j++) {
                float4 t = *(float4*)&Ks[(tx*4+j)*PAD + d0];
                bf[j][0] = t.x; bf[j][1] = t.y; bf[j][2] = t.z; bf[j][3] = t.w;
            }
#pragma unroll
            for (int dd = 0; dd < 4; dd++) {
                ulonglong2 aA = *(ulonglong2*)&Qs[(d0+dd)*PAD + ty*8];
                ulonglong2 aB = *(ulonglong2*)&Qs[(d0+dd)*PAD + ty*8 + 4];
                u64 ap[4] = {aA.x, aA.y, aB.x, aB.y};
#pragma unroll
                for (int j = 0; j < 4; j++) {
                    u64 bb = pack2(bf[j][dd], bf[j][dd]);
                    c2[0][j] = fma2(ap[0], bb, c2[0][j]);
                    c2[1][j] = fma2(ap[1], bb, c2[1][j]);
                    c2[2][j] = fma2(ap[2], bb, c2[2][j]);
                    c2[3][j] = fma2(ap[3], bb, c2[3][j]);
                }
            }
        }

        // ---- scale + causal mask ----
        float s[8][4];
#pragma unroll
        for (int p = 0; p < 4; p++)
#pragma unroll
            for (int j = 0; j < 4; j++)
                unpack2(c2[p][j], s[2*p][j], s[2*p+1][j]);

        const bool diag = (k0 == q0);
#pragma unroll
        for (int i = 0; i < 8; i++)
#pragma unroll
            for (int j = 0; j < 4; j++) {
                float v = s[i][j] * 0.125f;
                if (diag && (k0 + tx*4 + j > q0 + ty*8 + i)) v = -INFINITY;
                s[i][j] = v;
            }

        // ---- gated bit-exact noise: only keys within 20 of running max ----
        {
            unsigned kb = (unsigned)(k0 + tx*4);
#pragma unroll
            for (int i = 0; i < 8; i++) {
                float thr = m[i] - 20.0f;
#pragma unroll
                for (int j = 0; j < 4; j++)
                    if (s[i][j] > thr)
                        s[i][j] += jax_noise_at(rowb[i] + kb + j);
            }
        }

        // ---- online softmax update (per-row state, width-16 shfl) ----
        float corr[8];
#pragma unroll
        for (int i = 0; i < 8; i++) {
            float rm = fmaxf(fmaxf(s[i][0], s[i][1]), fmaxf(s[i][2], s[i][3]));
            rm = fmaxf(rm, __shfl_xor_sync(0xffffffffu, rm, 1, 16));
            rm = fmaxf(rm, __shfl_xor_sync(0xffffffffu, rm, 2, 16));
            rm = fmaxf(rm, __shfl_xor_sync(0xffffffffu, rm, 4, 16));
            rm = fmaxf(rm, __shfl_xor_sync(0xffffffffu, rm, 8, 16));
            float mn = fmaxf(m[i], rm);
            corr[i] = __expf(m[i] - mn);      // 0 on first chunk
            m[i] = mn;
            float ps = 0.0f;
#pragma unroll
            for (int j = 0; j < 4; j++) {
                float pv = __expf(s[i][j] - mn);   // masked -> 0
                s[i][j] = pv;
                ps += pv;
            }
            lp[i] = lp[i] * corr[i] + ps;
        }
#pragma unroll
        for (int p = 0; p < 4; p++) {
            u64 cc = pack2(corr[2*p], corr[2*p+1]);
#pragma unroll
            for (int j = 0; j < 4; j++) O2[p][j] = mul2(O2[p][j], cc);
        }

        // ---- P -> smem [k][q] ----
#pragma unroll
        for (int j = 0; j < 4; j++) {
            *(float4*)&Ps[(tx*4+j)*PAD + ty*8] =
                make_float4(s[0][j], s[1][j], s[2][j], s[3][j]);
            *(float4*)&Ps[(tx*4+j)*PAD + ty*8 + 4] =
                make_float4(s[4][j], s[5][j], s[6][j], s[7][j]);
        }
        __syncthreads();

        // ---- AV GEMM: O[8 rows x 4 dims] += P * V ----
        for (int kk = 0; kk < 64; kk++) {
            float4 bv = *(float4*)&Vs[kk*PAD + tx*4];
            ulonglong2 aA = *(ulonglong2*)&Ps[kk*PAD + ty*8];
            ulonglong2 aB = *(ulonglong2*)&Ps[kk*PAD + ty*8 + 4];
            u64 ap[4] = {aA.x, aA.y, aB.x, aB.y};
            u64 b0 = pack2(bv.x, bv.x);
            u64 b1 = pack2(bv.y, bv.y);
            u64 b2 = pack2(bv.z, bv.z);
            u64 b3 = pack2(bv.w, bv.w);
#pragma unroll
            for (int p = 0; p < 4; p++) {
                O2[p][0] = fma2(ap[p], b0, O2[p][0]);
                O2[p][1] = fma2(ap[p], b1, O2[p][1]);
                O2[p][2] = fma2(ap[p], b2, O2[p][2]);
                O2[p][3] = fma2(ap[p], b3, O2[p][3]);
            }
        }
    }

    // ---- finalize: reduce l across the 16-lane row group, store Z ----
    float inv[8];
#pragma unroll
    for (int i = 0; i < 8; i++) {
        float l = lp[i];
        l += __shfl_xor_sync(0xffffffffu, l, 1, 16);
        l += __shfl_xor_sync(0xffffffffu, l, 2, 16);
        l += __shfl_xor_sync(0xffffffffu, l, 4, 16);
        l += __shfl_xor_sync(0xffffffffu, l, 8, 16);
        inv[i] = 1.0f / l;
    }
#pragma unroll
    for (int p = 0; p < 4; p++) {
        float lo[4], hi[4];
#pragma unroll
        for (int j = 0; j < 4; j++) unpack2(O2[p][j], lo[j], hi[j]);
        int r0 = ty*8 + 2*p;
        float4 v0 = make_float4(lo[0]*inv[2*p], lo[1]*inv[2*p],
                                lo[2]*inv[2*p], lo[3]*inv[2*p]);
        float4 v1 = make_float4(hi[0]*inv[2*p+1], hi[1]*inv[2*p+1],
                                hi[2]*inv[2*p+1], hi[3]*inv[2*p+1]);
        *(float4*)(g_Z + (bh + q0 + r0    )*DH + tx*4) = v0;
        *(float4*)(g_Z + (bh + q0 + r0 + 1)*DH + tx*4) = v1;
    }
}

// ---------------------------------------------------------------------------
// Kernel C: output projection. 128x64 tile, 256 threads, 4m x 8n micro-tile.
// Same scheme as Kernel A; K dim = (h,e) gathered from g_Z.
// grid: (32 mtiles, 16 ntiles)
// ---------------------------------------------------------------------------
__global__ __launch_bounds__(256) void oproj_kernel(
    const float* __restrict__ Wo, const float* __restrict__ bo,
    float* __restrict__ out)
{
    __shared__ float Zs[128][36];
    __shared__ float Ws[32][64];

    const int m0 = blockIdx.x * 128;
    const int n0 = blockIdx.y * 64;
    const int tid = threadIdx.x;
    const int tx = tid & 7;
    const int ty = tid >> 3;

    u64 c2[4][4];
#pragma unroll
    for (int i = 0; i < 4; i++)
#pragma unroll
        for (int j = 0; j < 4; j++) c2[i][j] = 0ull;

    for (int k0 = 0; k0 < NH*DH; k0 += 32) {
        const int hh = k0 >> 6;
        const int e0 = k0 & 63;
        __syncthreads();
        // Z tile: 128 rows x 32 k-cols, natural layout. 4 float4/thread.
#pragma unroll
        for (int i = 0; i < 4; i++) {
            int f = tid + i * 256;
            int r = f >> 3, c4 = (f & 7) * 4;
            int n = m0 + r;
            int bb = n >> 11;
            int t  = n & (NT - 1);
            *(float4*)&Zs[r][c4] =
                *(const float4*)(g_Z + (((size_t)(bb*NH + hh))*NT + t)*DH + e0 + c4);
        }
        // Wo tile: 32 x 64. 2 float4/thread.
#pragma unroll
        for (int i = 0; i < 2; i++) {
            int f = tid + i * 256;
            int r = f >> 4, c4 = (f & 15) * 4;
            *(float4*)&Ws[r][c4] = *(const float4*)(Wo + (size_t)(k0 + r)*ND + n0 + c4);
        }
        __syncthreads();
#pragma unroll 8
        for (int kk = 0; kk < 32; kk++) {
            ulonglong2 bA = *(const ulonglong2*)&Ws[kk][tx*4];
            ulonglong2 bB = *(const ulonglong2*)&Ws[kk][32 + tx*4];
#pragma unroll
            for (int i = 0; i < 4; i++) {
                float av = Zs[ty*4 + i][kk];
                u64 ai = pack2(av, av);
                c2[i][0] = fma2(ai, bA.x, c2[i][0]);
                c2[i][1] = fma2(ai, bA.y, c2[i][1]);
                c2[i][2] = fma2(ai, bB.x, c2[i][2]);
                c2[i][3] = fma2(ai, bB.y, c2[i][3]);
            }
        }
    }

    float4 boA = *(const float4*)(bo + n0 + tx*4);
    float4 boB = *(const float4*)(bo + n0 + 32 + tx*4);
#pragma unroll
    for (int i = 0; i < 4; i++) {
        int n = m0 + ty*4 + i;
        float* orow = out + (size_t)n*ND + n0;
        float4 rA, rB;
        unpack2(c2[i][0], rA.x, rA.y);
        unpack2(c2[i][1], rA.z, rA.w);
        unpack2(c2[i][2], rB.x, rB.y);
        unpack2(c2[i][3], rB.z, rB.w);
        rA.x += boA.x; rA.y += boA.y; rA.z += boA.z; rA.w += boA.w;
        rB.x += boB.x; rB.y += boB.y; rB.z += boB.z; rB.w += boB.w;
        *(float4*)(orow + tx*4)      = rA;
        *(float4*)(orow + 32 + tx*4) = rB;
    }
}

// ---------------------------------------------------------------------------
extern "C" void kernel_launch(void* const* d_in, const int* in_sizes, int n_in,
                              void* d_out, int out_size)
{
    (void)in_sizes; (void)n_in; (void)out_size;
    const float* X  = (const float*)d_in[0];
    const float* Wq = (const float*)d_in[1];
    const float* Wk = (const float*)d_in[2];
    const float* Wv = (const float*)d_in[3];
    const float* Wo = (const float*)d_in[4];
    const float* bq = (const float*)d_in[5];
    const float* bk = (const float*)d_in[6];
    const float* bv = (const float*)d_in[7];
    const float* bo = (const float*)d_in[8];
    float* out = (float*)d_out;

    cudaFuncSetAttribute(attn_kernel,
                         cudaFuncAttributeMaxDynamicSharedMemorySize, ATTN_SMEM);

    qkv_kernel<<<dim3(32, 16, 3), 256>>>(X, Wq, Wk, Wv, bq, bk, bv);
    attn_kernel<<<dim3(32, 16, 2), 128, ATTN_SMEM>>>();
    oproj_kernel<<<dim3(32, 16), 256>>>(Wo, bo, out);
}

// round 14
// speedup vs baseline: 1.2405x; 1.2311x over previous
#include <cuda_runtime.h>
#include <cuda_bf16.h>
#include <cstdint>
#include <math.h>

#define NB 2
#define NH 16
#define NT 2048
#define ND 1024
#define DH 64
#define PAD 68

typedef unsigned long long u64;

// Scratch (allocation-free): Q,K,V,Z in [B][H][T][Dh] layout, fp32. 16 MB each.
__device__ float g_Q[NB*NH*NT*DH];
__device__ float g_K[NB*NH*NT*DH];
__device__ float g_V[NB*NH*NT*DH];
__device__ float g_Z[NB*NH*NT*DH];

// bf16 hi/lo splits (precomputed once per launch)
__device__ __nv_bfloat16 g_Xhi[NB*NT*ND];        // [4096][1024]
__device__ __nv_bfloat16 g_Xlo[NB*NT*ND];
__device__ __nv_bfloat16 g_Whi[3*NH*ND*DH];      // [p][h][k][n]
__device__ __nv_bfloat16 g_Wlo[3*NH*ND*DH];

// ---------------------------------------------------------------------------
// Packed f32x2 helpers (Blackwell FFMA2 path)
// ---------------------------------------------------------------------------
__device__ __forceinline__ u64 pack2(float lo, float hi)
{ u64 r; asm("mov.b64 %0, {%1, %2};" : "=l"(r) : "f"(lo), "f"(hi)); return r; }

__device__ __forceinline__ u64 fma2(u64 a, u64 b, u64 c)
{ u64 d; asm("fma.rn.f32x2 %0, %1, %2, %3;" : "=l"(d) : "l"(a), "l"(b), "l"(c)); return d; }

__device__ __forceinline__ u64 mul2(u64 a, u64 b)
{ u64 d; asm("mul.rn.f32x2 %0, %1, %2;" : "=l"(d) : "l"(a), "l"(b)); return d; }

__device__ __forceinline__ void unpack2(u64 v, float& lo, float& hi)
{ asm("mov.b64 {%0, %1}, %2;" : "=f"(lo), "=f"(hi) : "l"(v)); }

// ---------------------------------------------------------------------------
// mma.sync / ldmatrix helpers (sm_80 baseline — works on compute_103)
// ---------------------------------------------------------------------------
__device__ __forceinline__ uint32_t smem_u32(const void* p)
{
    uint32_t a;
    asm("{ .reg .u64 t; cvta.to.shared.u64 t, %1; cvt.u32.u64 %0, t; }"
        : "=r"(a) : "l"(p));
    return a;
}

__device__ __forceinline__ void ldsm_x4(uint32_t* r, uint32_t a)
{
    asm volatile("ldmatrix.sync.aligned.m8n8.x4.shared.b16 {%0,%1,%2,%3}, [%4];"
                 : "=r"(r[0]), "=r"(r[1]), "=r"(r[2]), "=r"(r[3]) : "r"(a));
}

__device__ __forceinline__ void ldsm_x4_t(uint32_t* r, uint32_t a)
{
    asm volatile("ldmatrix.sync.aligned.m8n8.x4.trans.shared.b16 {%0,%1,%2,%3}, [%4];"
                 : "=r"(r[0]), "=r"(r[1]), "=r"(r[2]), "=r"(r[3]) : "r"(a));
}

__device__ __forceinline__ void mma16816(float* c, const uint32_t* a,
                                         uint32_t b0, uint32_t b1)
{
    asm volatile(
        "mma.sync.aligned.m16n8k16.row.col.f32.bf16.bf16.f32 "
        "{%0,%1,%2,%3},{%4,%5,%6,%7},{%8,%9},{%0,%1,%2,%3};"
        : "+f"(c[0]), "+f"(c[1]), "+f"(c[2]), "+f"(c[3])
        : "r"(a[0]), "r"(a[1]), "r"(a[2]), "r"(a[3]), "r"(b0), "r"(b1));
}

// ---------------------------------------------------------------------------
// JAX threefry2x32 with key (0, 42)
// ---------------------------------------------------------------------------
__device__ __forceinline__ void threefry_0_42(unsigned x0, unsigned x1,
                                              unsigned &o0, unsigned &o1)
{
    const unsigned ks0 = 0u;
    const unsigned ks1 = 42u;
    const unsigned ks2 = 0x1BD11BDAu ^ 42u;
    x0 += ks0; x1 += ks1;
#define TF_R(r) do { x0 += x1; x1 = __funnelshift_l(x1, x1, (r)); x1 ^= x0; } while (0)
    TF_R(13); TF_R(15); TF_R(26); TF_R(6);
    x0 += ks1; x1 += ks2 + 1u;
    TF_R(17); TF_R(29); TF_R(16); TF_R(24);
    x0 += ks2; x1 += ks0 + 2u;
    TF_R(13); TF_R(15); TF_R(26); TF_R(6);
    x0 += ks0; x1 += ks1 + 3u;
    TF_R(17); TF_R(29); TF_R(16); TF_R(24);
    x0 += ks1; x1 += ks2 + 4u;
    TF_R(13); TF_R(15); TF_R(26); TF_R(6);
    x0 += ks2; x1 += ks0 + 5u;
#undef TF_R
    o0 = x0; o1 = x1;
}

__device__ __forceinline__ float noise_from_bits(unsigned bits)
{
    float u = __uint_as_float((bits >> 9) | 0x3f800000u) - 1.0f;   // [0,1)
    const float lo = -0.99999994f;                                 // nextafter(-1,0)
    float v = fmaf(u, 2.0f, lo);
    v = fmaxf(v, lo);
    return 1.4142135623730951f * erfinvf(v) * 0.01f;
}

// JAX partitionable threefry: counter (0, flat_idx); draw = out0 ^ out1
__device__ __noinline__ float jax_noise_at(unsigned flat_idx)
{
    unsigned o0, o1;
    threefry_0_42(0u, flat_idx, o0, o1);
    return noise_from_bits(o0 ^ o1);
}

// ---------------------------------------------------------------------------
// Split kernels: fp32 -> bf16 hi + lo residual.
// ---------------------------------------------------------------------------
__device__ __forceinline__ void split4(float4 v, __nv_bfloat162& h0, __nv_bfloat162& h1,
                                       __nv_bfloat162& l0, __nv_bfloat162& l1)
{
    h0 = __floats2bfloat162_rn(v.x, v.y);
    h1 = __floats2bfloat162_rn(v.z, v.w);
    l0 = __floats2bfloat162_rn(v.x - __bfloat162float(h0.x),
                               v.y - __bfloat162float(h0.y));
    l1 = __floats2bfloat162_rn(v.z - __bfloat162float(h1.x),
                               v.w - __bfloat162float(h1.y));
}

__global__ __launch_bounds__(256) void split_x_kernel(const float* __restrict__ X)
{
    int i = (blockIdx.x * 256 + threadIdx.x) * 4;
    float4 v = *(const float4*)(X + i);
    __nv_bfloat162 h0, h1, l0, l1;
    split4(v, h0, h1, l0, l1);
    *(__nv_bfloat162*)(g_Xhi + i)     = h0;
    *(__nv_bfloat162*)(g_Xhi + i + 2) = h1;
    *(__nv_bfloat162*)(g_Xlo + i)     = l0;
    *(__nv_bfloat162*)(g_Xlo + i + 2) = l1;
}

__global__ __launch_bounds__(256) void split_w_kernel(
    const float* __restrict__ Wq, const float* __restrict__ Wk,
    const float* __restrict__ Wv)
{
    const float* W = (blockIdx.y == 0) ? Wq : (blockIdx.y == 1) ? Wk : Wv;
    size_t base = (size_t)blockIdx.y * NH * ND * DH;
    int i = (blockIdx.x * 256 + threadIdx.x) * 4;
    float4 v = *(const float4*)(W + i);
    __nv_bfloat162 h0, h1, l0, l1;
    split4(v, h0, h1, l0, l1);
    *(__nv_bfloat162*)(g_Whi + base + i)     = h0;
    *(__nv_bfloat162*)(g_Whi + base + i + 2) = h1;
    *(__nv_bfloat162*)(g_Wlo + base + i)     = l0;
    *(__nv_bfloat162*)(g_Wlo + base + i + 2) = l1;
}

// ---------------------------------------------------------------------------
// Kernel A: QKV projections via mma.sync bf16 3-term split.
// grid (32 mtiles, 16 heads, 3 proj), 256 threads = 8 warps.
// Warp w: rows m0+w*16..+15, all 64 cols (8 m16n8 tiles).
// K swept in 16 chunks of 64; smem rows padded to 72 bf16 (144 B: 16B-aligned,
// conflict-free ldmatrix).
// ---------------------------------------------------------------------------
#define XPAD 72
#define XHI_OFF 0
#define XLO_OFF (128*XPAD*2)
#define WHI_OFF (2*128*XPAD*2)
#define WLO_OFF (WHI_OFF + 64*XPAD*2)
#define QKV_SMEM (WLO_OFF + 64*XPAD*2)      // 55296 B

__global__ __launch_bounds__(256) void qkv_mma_kernel(
    const float* __restrict__ bq, const float* __restrict__ bk,
    const float* __restrict__ bv)
{
    extern __shared__ char sm[];
    __nv_bfloat16* Xhi_s = (__nv_bfloat16*)(sm + XHI_OFF);
    __nv_bfloat16* Xlo_s = (__nv_bfloat16*)(sm + XLO_OFF);
    __nv_bfloat16* Whi_s = (__nv_bfloat16*)(sm + WHI_OFF);
    __nv_bfloat16* Wlo_s = (__nv_bfloat16*)(sm + WLO_OFF);
    const uint32_t smb = smem_u32(sm);

    const int tid  = threadIdx.x;
    const int lane = tid & 31;
    const int w    = tid >> 5;
    const int m0   = blockIdx.x * 128;
    const int h    = blockIdx.y;
    const int which = blockIdx.z;

    const size_t wbase = ((size_t)which * NH + h) * ND * DH;
    const float* bias = (which == 0) ? bq : (which == 1) ? bk : bv;
    float* out = (which == 0) ? g_Q : (which == 1) ? g_K : g_V;

    // per-lane ldmatrix addresses
    const int a_row  = w*16 + (lane & 7) + ((lane & 8) ? 8 : 0);
    const int a_kadd = (lane & 16) ? 8 : 0;
    const uint32_t aaddr_hi0 = smb + XHI_OFF + (a_row*XPAD + a_kadd)*2;
    const uint32_t aaddr_lo0 = smb + XLO_OFF + (a_row*XPAD + a_kadd)*2;
    const int b_k    = (lane & 7) + ((lane & 8) ? 8 : 0);
    const int b_nadd = (lane & 16) ? 8 : 0;
    const uint32_t baddr_hi0 = smb + WHI_OFF + (b_k*XPAD + b_nadd)*2;
    const uint32_t baddr_lo0 = smb + WLO_OFF + (b_k*XPAD + b_nadd)*2;

    float c[8][4];
#pragma unroll
    for (int i = 0; i < 8; i++)
#pragma unroll
        for (int j = 0; j < 4; j++) c[i][j] = 0.0f;

    for (int kc = 0; kc < 16; kc++) {
        const int k0 = kc * 64;
        __syncthreads();
        // X tiles: 128 rows x 64 bf16 (one uint4 = 8 bf16); 1024 uint4, 4/thread
#pragma unroll
        for (int i = 0; i < 4; i++) {
            int f = tid + i * 256;
            int r = f >> 3, c8 = (f & 7) * 8;
            *(uint4*)&Xhi_s[r*XPAD + c8] =
                *(const uint4*)&g_Xhi[(size_t)(m0 + r)*ND + k0 + c8];
            *(uint4*)&Xlo_s[r*XPAD + c8] =
                *(const uint4*)&g_Xlo[(size_t)(m0 + r)*ND + k0 + c8];
        }
        // W tiles: 64 rows x 64 bf16; 512 uint4, 2/thread
#pragma unroll
        for (int i = 0; i < 2; i++) {
            int f = tid + i * 256;
            int r = f >> 3, c8 = (f & 7) * 8;
            *(uint4*)&Whi_s[r*XPAD + c8] =
                *(const uint4*)&g_Whi[wbase + (size_t)(k0 + r)*DH + c8];
            *(uint4*)&Wlo_s[r*XPAD + c8] =
                *(const uint4*)&g_Wlo[wbase + (size_t)(k0 + r)*DH + c8];
        }
        __syncthreads();

#pragma unroll
        for (int ks = 0; ks < 4; ks++) {
            uint32_t ahi[4], alo[4];
            ldsm_x4(ahi, aaddr_hi0 + ks*32);
            ldsm_x4(alo, aaddr_lo0 + ks*32);
            const uint32_t bk_off = ks * 16 * XPAD * 2;
#pragma unroll
            for (int nt = 0; nt < 4; nt++) {
                uint32_t bhi[4], blo[4];
                ldsm_x4_t(bhi, baddr_hi0 + bk_off + nt*32);
                ldsm_x4_t(blo, baddr_lo0 + bk_off + nt*32);
                mma16816(c[nt*2],     ahi, bhi[0], bhi[1]);
                mma16816(c[nt*2 + 1], ahi, bhi[2], bhi[3]);
                mma16816(c[nt*2],     ahi, blo[0], blo[1]);
                mma16816(c[nt*2 + 1], ahi, blo[2], blo[3]);
                mma16816(c[nt*2],     alo, bhi[0], bhi[1]);
                mma16816(c[nt*2 + 1], alo, bhi[2], bhi[3]);
            }
        }
    }

    // epilogue: fragment (g, tc) -> rows m0+w*16+g / +8
    const int g  = lane >> 2;
    const int tc = (lane & 3) * 2;
    const int mr0 = m0 + w*16 + g;
    const int mr1 = mr0 + 8;
    float* row0 = out + (((size_t)((mr0 >> 11)*NH + h))*NT + (mr0 & (NT-1)))*DH;
    float* row1 = out + (((size_t)((mr1 >> 11)*NH + h))*NT + (mr1 & (NT-1)))*DH;
    const float* bs = bias + h*DH;
#pragma unroll
    for (int nt = 0; nt < 8; nt++) {
        int col = nt*8 + tc;
        float2 v0 = make_float2(c[nt][0] + bs[col], c[nt][1] + bs[col+1]);
        float2 v1 = make_float2(c[nt][2] + bs[col], c[nt][3] + bs[col+1]);
        *(float2*)(row0 + col) = v0;
        *(float2*)(row1 + col) = v1;
    }
}

// ---------------------------------------------------------------------------
// Kernel B: block-tiled flash attention.  [unchanged — passing]
// ---------------------------------------------------------------------------
#define ATTN_SMEM (4*64*PAD*4)

__global__ __launch_bounds__(128, 3) void attn_kernel()
{
    extern __shared__ float smbuf[];
    float* Qs = smbuf;               // [d][q]
    float* Ks = smbuf + 64*PAD;      // [k][d]
    float* Vs = smbuf + 2*64*PAD;    // [k][e]
    float* Ps = smbuf + 3*64*PAD;    // [k][q]

    const int qt  = 31 - blockIdx.x;     // heavy q-tiles first
    const int h   = blockIdx.y;
    const int b   = blockIdx.z;
    const int tid = threadIdx.x;
    const int tx  = tid & 15;
    const int ty  = tid >> 4;
    const int q0  = qt * 64;
    const size_t bh = ((size_t)(b*NH + h))*NT;

#pragma unroll
    for (int i2 = 0; i2 < 8; i2++) {
        int f = tid + i2*128;
        int r = f >> 4, d4 = (f & 15)*4;
        float4 v = *(const float4*)(g_Q + (bh + q0 + r)*DH + d4);
        Qs[(d4+0)*PAD + r] = v.x;
        Qs[(d4+1)*PAD + r] = v.y;
        Qs[(d4+2)*PAD + r] = v.z;
        Qs[(d4+3)*PAD + r] = v.w;
    }

    float m[8], lp[8];
    unsigned rowb[8];
    u64 O2[4][4];
#pragma unroll
    for (int i = 0; i < 8; i++) {
        m[i] = -INFINITY; lp[i] = 0.0f;
        rowb[i] = ((unsigned)b << 26)
                + (unsigned)(h*NT + q0 + ty*8 + i) * (unsigned)NT;
    }
#pragma unroll
    for (int p = 0; p < 4; p++)
#pragma unroll
        for (int j = 0; j < 4; j++) O2[p][j] = 0ull;

    for (int k0 = 0; k0 <= q0; k0 += 64) {
        __syncthreads();
#pragma unroll
        for (int i2 = 0; i2 < 8; i2++) {
            int f = tid + i2*128;
            int r = f >> 4, d4 = (f & 15)*4;
            size_t off = (bh + k0 + r)*DH + d4;
            *(float4*)&Ks[r*PAD + d4] = *(const float4*)(g_K + off);
            *(float4*)&Vs[r*PAD + d4] = *(const float4*)(g_V + off);
        }
        __syncthreads();

        u64 c2[4][4];
#pragma unroll
        for (int p = 0; p < 4; p++)
#pragma unroll
            for (int j = 0; j < 4; j++) c2[p][j] = 0ull;

        for (int d0 = 0; d0 < DH; d0 += 4) {
            float bf[4][4];
#pragma unroll
            for (int j = 0; j < 4; j++) {
                float4 t = *(float4*)&Ks[(tx*4+j)*PAD + d0];
                bf[j][0] = t.x; bf[j][1] = t.y; bf[j][2] = t.z; bf[j][3] = t.w;
            }
#pragma unroll
            for (int dd = 0; dd < 4; dd++) {
                ulonglong2 aA = *(ulonglong2*)&Qs[(d0+dd)*PAD + ty*8];
                ulonglong2 aB = *(ulonglong2*)&Qs[(d0+dd)*PAD + ty*8 + 4];
                u64 ap[4] = {aA.x, aA.y, aB.x, aB.y};
#pragma unroll
                for (int j = 0; j < 4; j++) {
                    u64 bb = pack2(bf[j][dd], bf[j][dd]);
                    c2[0][j] = fma2(ap[0], bb, c2[0][j]);
                    c2[1][j] = fma2(ap[1], bb, c2[1][j]);
                    c2[2][j] = fma2(ap[2], bb, c2[2][j]);
                    c2[3][j] = fma2(ap[3], bb, c2[3][j]);
                }
            }
        }

        float s[8][4];
#pragma unroll
        for (int p = 0; p < 4; p++)
#pragma unroll
            for (int j = 0; j < 4; j++)
                unpack2(c2[p][j], s[2*p][j], s[2*p+1][j]);

        const bool diag = (k0 == q0);
#pragma unroll
        for (int i = 0; i < 8; i++)
#pragma unroll
            for (int j = 0; j < 4; j++) {
                float v = s[i][j] * 0.125f;
                if (diag && (k0 + tx*4 + j > q0 + ty*8 + i)) v = -INFINITY;
                s[i][j] = v;
            }

        {
            unsigned kb = (unsigned)(k0 + tx*4);
#pragma unroll
            for (int i = 0; i < 8; i++) {
                float thr = m[i] - 20.0f;
#pragma unroll
                for (int j = 0; j < 4; j++)
                    if (s[i][j] > thr)
                        s[i][j] += jax_noise_at(rowb[i] + kb + j);
            }
        }

        float corr[8];
#pragma unroll
        for (int i = 0; i < 8; i++) {
            float rm = fmaxf(fmaxf(s[i][0], s[i][1]), fmaxf(s[i][2], s[i][3]));
            rm = fmaxf(rm, __shfl_xor_sync(0xffffffffu, rm, 1, 16));
            rm = fmaxf(rm, __shfl_xor_sync(0xffffffffu, rm, 2, 16));
            rm = fmaxf(rm, __shfl_xor_sync(0xffffffffu, rm, 4, 16));
            rm = fmaxf(rm, __shfl_xor_sync(0xffffffffu, rm, 8, 16));
            float mn = fmaxf(m[i], rm);
            corr[i] = __expf(m[i] - mn);
            m[i] = mn;
            float ps = 0.0f;
#pragma unroll
            for (int j = 0; j < 4; j++) {
                float pv = __expf(s[i][j] - mn);
                s[i][j] = pv;
                ps += pv;
            }
            lp[i] = lp[i] * corr[i] + ps;
        }
#pragma unroll
        for (int p = 0; p < 4; p++) {
            u64 cc = pack2(corr[2*p], corr[2*p+1]);
#pragma unroll
            for (int j = 0; j < 4; j++) O2[p][j] = mul2(O2[p][j], cc);
        }

#pragma unroll
        for (int j = 0; j < 4; j++) {
            *(float4*)&Ps[(tx*4+j)*PAD + ty*8] =
                make_float4(s[0][j], s[1][j], s[2][j], s[3][j]);
            *(float4*)&Ps[(tx*4+j)*PAD + ty*8 + 4] =
                make_float4(s[4][j], s[5][j], s[6][j], s[7][j]);
        }
        __syncthreads();

        for (int kk = 0; kk < 64; kk++) {
            float4 bv = *(float4*)&Vs[kk*PAD + tx*4];
            ulonglong2 aA = *(ulonglong2*)&Ps[kk*PAD + ty*8];
            ulonglong2 aB = *(ulonglong2*)&Ps[kk*PAD + ty*8 + 4];
            u64 ap[4] = {aA.x, aA.y, aB.x, aB.y};
            u64 b0 = pack2(bv.x, bv.x);
            u64 b1 = pack2(bv.y, bv.y);
            u64 b2 = pack2(bv.z, bv.z);
            u64 b3 = pack2(bv.w, bv.w);
#pragma unroll
            for (int p = 0; p < 4; p++) {
                O2[p][0] = fma2(ap[p], b0, O2[p][0]);
                O2[p][1] = fma2(ap[p], b1, O2[p][1]);
                O2[p][2] = fma2(ap[p], b2, O2[p][2]);
                O2[p][3] = fma2(ap[p], b3, O2[p][3]);
            }
        }
    }

    float inv[8];
#pragma unroll
    for (int i = 0; i < 8; i++) {
        float l = lp[i];
        l += __shfl_xor_sync(0xffffffffu, l, 1, 16);
        l += __shfl_xor_sync(0xffffffffu, l, 2, 16);
        l += __shfl_xor_sync(0xffffffffu, l, 4, 16);
        l += __shfl_xor_sync(0xffffffffu, l, 8, 16);
        inv[i] = 1.0f / l;
    }
#pragma unroll
    for (int p = 0; p < 4; p++) {
        float lo[4], hi[4];
#pragma unroll
        for (int j = 0; j < 4; j++) unpack2(O2[p][j], lo[j], hi[j]);
        int r0 = ty*8 + 2*p;
        float4 v0 = make_float4(lo[0]*inv[2*p], lo[1]*inv[2*p],
                                lo[2]*inv[2*p], lo[3]*inv[2*p]);
        float4 v1 = make_float4(hi[0]*inv[2*p+1], hi[1]*inv[2*p+1],
                                hi[2]*inv[2*p+1], hi[3]*inv[2*p+1]);
        *(float4*)(g_Z + (bh + q0 + r0    )*DH + tx*4) = v0;
        *(float4*)(g_Z + (bh + q0 + r0 + 1)*DH + tx*4) = v1;
    }
}

// ---------------------------------------------------------------------------
// Kernel C: output projection. 128x64 tile, 256 threads, 4m x 8n micro-tile.
// [unchanged — passing]
// ---------------------------------------------------------------------------
__global__ __launch_bounds__(256) void oproj_kernel(
    const float* __restrict__ Wo, const float* __restrict__ bo,
    float* __restrict__ out)
{
    __shared__ float Zs[128][36];
    __shared__ float Ws[32][64];

    const int m0 = blockIdx.x * 128;
    const int n0 = blockIdx.y * 64;
    const int tid = threadIdx.x;
    const int tx = tid & 7;
    const int ty = tid >> 3;

    u64 c2[4][4];
#pragma unroll
    for (int i = 0; i < 4; i++)
#pragma unroll
        for (int j = 0; j < 4; j++) c2[i][j] = 0ull;

    for (int k0 = 0; k0 < NH*DH; k0 += 32) {
        const int hh = k0 >> 6;
        const int e0 = k0 & 63;
        __syncthreads();
#pragma unroll
        for (int i = 0; i < 4; i++) {
            int f = tid + i * 256;
            int r = f >> 3, c4 = (f & 7) * 4;
            int n = m0 + r;
            int bb = n >> 11;
            int t  = n & (NT - 1);
            *(float4*)&Zs[r][c4] =
                *(const float4*)(g_Z + (((size_t)(bb*NH + hh))*NT + t)*DH + e0 + c4);
        }
#pragma unroll
        for (int i = 0; i < 2; i++) {
            int f = tid + i * 256;
            int r = f >> 4, c4 = (f & 15) * 4;
            *(float4*)&Ws[r][c4] = *(const float4*)(Wo + (size_t)(k0 + r)*ND + n0 + c4);
        }
        __syncthreads();
#pragma unroll 8
        for (int kk = 0; kk < 32; kk++) {
            ulonglong2 bA = *(const ulonglong2*)&Ws[kk][tx*4];
            ulonglong2 bB = *(const ulonglong2*)&Ws[kk][32 + tx*4];
#pragma unroll
            for (int i = 0; i < 4; i++) {
                float av = Zs[ty*4 + i][kk];
                u64 ai = pack2(av, av);
                c2[i][0] = fma2(ai, bA.x, c2[i][0]);
                c2[i][1] = fma2(ai, bA.y, c2[i][1]);
                c2[i][2] = fma2(ai, bB.x, c2[i][2]);
                c2[i][3] = fma2(ai, bB.y, c2[i][3]);
            }
        }
    }

    float4 boA = *(const float4*)(bo + n0 + tx*4);
    float4 boB = *(const float4*)(bo + n0 + 32 + tx*4);
#pragma unroll
    for (int i = 0; i < 4; i++) {
        int n = m0 + ty*4 + i;
        float* orow = out + (size_t)n*ND + n0;
        float4 rA, rB;
        unpack2(c2[i][0], rA.x, rA.y);
        unpack2(c2[i][1], rA.z, rA.w);
        unpack2(c2[i][2], rB.x, rB.y);
        unpack2(c2[i][3], rB.z, rB.w);
        rA.x += boA.x; rA.y += boA.y; rA.z += boA.z; rA.w += boA.w;
        rB.x += boB.x; rB.y += boB.y; rB.z += boB.z; rB.w += boB.w;
        *(float4*)(orow + tx*4)      = rA;
        *(float4*)(orow + 32 + tx*4) = rB;
    }
}

// ---------------------------------------------------------------------------
extern "C" void kernel_launch(void* const* d_in, const int* in_sizes, int n_in,
                              void* d_out, int out_size)
{
    (void)in_sizes; (void)n_in; (void)out_size;
    const float* X  = (const float*)d_in[0];
    const float* Wq = (const float*)d_in[1];
    const float* Wk = (const float*)d_in[2];
    const float* Wv = (const float*)d_in[3];
    const float* Wo = (const float*)d_in[4];
    const float* bq = (const float*)d_in[5];
    const float* bk = (const float*)d_in[6];
    const float* bv = (const float*)d_in[7];
    const float* bo = (const float*)d_in[8];
    float* out = (float*)d_out;

    static int configured = 0;
    if (!configured) {
        cudaFuncSetAttribute(qkv_mma_kernel,
                             cudaFuncAttributeMaxDynamicSharedMemorySize, QKV_SMEM);
        cudaFuncSetAttribute(attn_kernel,
                             cudaFuncAttributeMaxDynamicSharedMemorySize, ATTN_SMEM);
        configured = 1;
    }

    split_x_kernel<<<NB*NT*ND/1024, 256>>>(X);
    split_w_kernel<<<dim3(NH*ND*DH/1024, 3), 256>>>(Wq, Wk, Wv);
    qkv_mma_kernel<<<dim3(32, 16, 3), 256, QKV_SMEM>>>(bq, bk, bv);
    attn_kernel<<<dim3(32, 16, 2), 128, ATTN_SMEM>>>();
    oproj_kernel<<<dim3(32, 16), 256>>>(Wo, bo, out);
}

// round 16
// speedup vs baseline: 1.6659x; 1.3429x over previous
#include <cuda_runtime.h>
#include <cuda_bf16.h>
#include <cstdint>
#include <math.h>

#define NB 2
#define NH 16
#define NT 2048
#define ND 1024
#define DH 64

typedef unsigned long long u64;

// Scratch (allocation-free).
__device__ float g_Z[NB*NH*NT*DH];                   // attention out (fp32, for oproj)
__device__ __nv_bfloat16 g_Qhi[NB*NH*NT*DH];
__device__ __nv_bfloat16 g_Qlo[NB*NH*NT*DH];
__device__ __nv_bfloat16 g_Khi[NB*NH*NT*DH];
__device__ __nv_bfloat16 g_Klo[NB*NH*NT*DH];
__device__ __nv_bfloat16 g_Vhi[NB*NH*NT*DH];
__device__ __nv_bfloat16 g_Vlo[NB*NH*NT*DH];
__device__ __nv_bfloat16 g_Xhi[NB*NT*ND];
__device__ __nv_bfloat16 g_Xlo[NB*NT*ND];
__device__ __nv_bfloat16 g_Whi[3*NH*ND*DH];
__device__ __nv_bfloat16 g_Wlo[3*NH*ND*DH];

// ---------------------------------------------------------------------------
// Packed f32x2 helpers (oproj)
// ---------------------------------------------------------------------------
__device__ __forceinline__ u64 pack2(float lo, float hi)
{ u64 r; asm("mov.b64 %0, {%1, %2};" : "=l"(r) : "f"(lo), "f"(hi)); return r; }

__device__ __forceinline__ u64 fma2(u64 a, u64 b, u64 c)
{ u64 d; asm("fma.rn.f32x2 %0, %1, %2, %3;" : "=l"(d) : "l"(a), "l"(b), "l"(c)); return d; }

__device__ __forceinline__ void unpack2(u64 v, float& lo, float& hi)
{ asm("mov.b64 {%0, %1}, %2;" : "=f"(lo), "=f"(hi) : "l"(v)); }

// ---------------------------------------------------------------------------
// mma.sync / ldmatrix helpers (sm_80 baseline — works on compute_103)
// ---------------------------------------------------------------------------
__device__ __forceinline__ uint32_t smem_u32(const void* p)
{
    uint32_t a;
    asm("{ .reg .u64 t; cvta.to.shared.u64 t, %1; cvt.u32.u64 %0, t; }"
        : "=r"(a) : "l"(p));
    return a;
}

__device__ __forceinline__ void ldsm_x4(uint32_t* r, uint32_t a)
{
    asm volatile("ldmatrix.sync.aligned.m8n8.x4.shared.b16 {%0,%1,%2,%3}, [%4];"
                 : "=r"(r[0]), "=r"(r[1]), "=r"(r[2]), "=r"(r[3]) : "r"(a));
}

__device__ __forceinline__ void ldsm_x4_t(uint32_t* r, uint32_t a)
{
    asm volatile("ldmatrix.sync.aligned.m8n8.x4.trans.shared.b16 {%0,%1,%2,%3}, [%4];"
                 : "=r"(r[0]), "=r"(r[1]), "=r"(r[2]), "=r"(r[3]) : "r"(a));
}

__device__ __forceinline__ void mma16816(float* c, const uint32_t* a,
                                         uint32_t b0, uint32_t b1)
{
    asm volatile(
        "mma.sync.aligned.m16n8k16.row.col.f32.bf16.bf16.f32 "
        "{%0,%1,%2,%3},{%4,%5,%6,%7},{%8,%9},{%0,%1,%2,%3};"
        : "+f"(c[0]), "+f"(c[1]), "+f"(c[2]), "+f"(c[3])
        : "r"(a[0]), "r"(a[1]), "r"(a[2]), "r"(a[3]), "r"(b0), "r"(b1));
}

// split two fp32 into packed bf16 hi pair + lo-residual pair
__device__ __forceinline__ void split2(float x, float y, uint32_t& hi, uint32_t& lo)
{
    __nv_bfloat162 h = __floats2bfloat162_rn(x, y);
    __nv_bfloat162 l = __floats2bfloat162_rn(x - __bfloat162float(h.x),
                                             y - __bfloat162float(h.y));
    hi = *(uint32_t*)&h;
    lo = *(uint32_t*)&l;
}

// ---------------------------------------------------------------------------
// JAX threefry2x32 with key (0, 42)
// ---------------------------------------------------------------------------
__device__ __forceinline__ void threefry_0_42(unsigned x0, unsigned x1,
                                              unsigned &o0, unsigned &o1)
{
    const unsigned ks0 = 0u;
    const unsigned ks1 = 42u;
    const unsigned ks2 = 0x1BD11BDAu ^ 42u;
    x0 += ks0; x1 += ks1;
#define TF_R(r) do { x0 += x1; x1 = __funnelshift_l(x1, x1, (r)); x1 ^= x0; } while (0)
    TF_R(13); TF_R(15); TF_R(26); TF_R(6);
    x0 += ks1; x1 += ks2 + 1u;
    TF_R(17); TF_R(29); TF_R(16); TF_R(24);
    x0 += ks2; x1 += ks0 + 2u;
    TF_R(13); TF_R(15); TF_R(26); TF_R(6);
    x0 += ks0; x1 += ks1 + 3u;
    TF_R(17); TF_R(29); TF_R(16); TF_R(24);
    x0 += ks1; x1 += ks2 + 4u;
    TF_R(13); TF_R(15); TF_R(26); TF_R(6);
    x0 += ks2; x1 += ks0 + 5u;
#undef TF_R
    o0 = x0; o1 = x1;
}

__device__ __forceinline__ float noise_from_bits(unsigned bits)
{
    float u = __uint_as_float((bits >> 9) | 0x3f800000u) - 1.0f;   // [0,1)
    const float lo = -0.99999994f;                                 // nextafter(-1,0)
    float v = fmaf(u, 2.0f, lo);
    v = fmaxf(v, lo);
    return 1.4142135623730951f * erfinvf(v) * 0.01f;
}

// JAX partitionable threefry: counter (0, flat_idx); draw = out0 ^ out1
__device__ __noinline__ float jax_noise_at(unsigned flat_idx)
{
    unsigned o0, o1;
    threefry_0_42(0u, flat_idx, o0, o1);
    return noise_from_bits(o0 ^ o1);
}

// ---------------------------------------------------------------------------
// Split kernels: fp32 -> bf16 hi + lo residual.
// ---------------------------------------------------------------------------
__device__ __forceinline__ void split4(float4 v, __nv_bfloat162& h0, __nv_bfloat162& h1,
                                       __nv_bfloat162& l0, __nv_bfloat162& l1)
{
    h0 = __floats2bfloat162_rn(v.x, v.y);
    h1 = __floats2bfloat162_rn(v.z, v.w);
    l0 = __floats2bfloat162_rn(v.x - __bfloat162float(h0.x),
                               v.y - __bfloat162float(h0.y));
    l1 = __floats2bfloat162_rn(v.z - __bfloat162float(h1.x),
                               v.w - __bfloat162float(h1.y));
}

__global__ __launch_bounds__(256) void split_x_kernel(const float* __restrict__ X)
{
    int i = (blockIdx.x * 256 + threadIdx.x) * 4;
    float4 v = *(const float4*)(X + i);
    __nv_bfloat162 h0, h1, l0, l1;
    split4(v, h0, h1, l0, l1);
    *(__nv_bfloat162*)(g_Xhi + i)     = h0;
    *(__nv_bfloat162*)(g_Xhi + i + 2) = h1;
    *(__nv_bfloat162*)(g_Xlo + i)     = l0;
    *(__nv_bfloat162*)(g_Xlo + i + 2) = l1;
}

__global__ __launch_bounds__(256) void split_w_kernel(
    const float* __restrict__ Wq, const float* __restrict__ Wk,
    const float* __restrict__ Wv)
{
    const float* W = (blockIdx.y == 0) ? Wq : (blockIdx.y == 1) ? Wk : Wv;
    size_t base = (size_t)blockIdx.y * NH * ND * DH;
    int i = (blockIdx.x * 256 + threadIdx.x) * 4;
    float4 v = *(const float4*)(W + i);
    __nv_bfloat162 h0, h1, l0, l1;
    split4(v, h0, h1, l0, l1);
    *(__nv_bfloat162*)(g_Whi + base + i)     = h0;
    *(__nv_bfloat162*)(g_Whi + base + i + 2) = h1;
    *(__nv_bfloat162*)(g_Wlo + base + i)     = l0;
    *(__nv_bfloat162*)(g_Wlo + base + i + 2) = l1;
}

// ---------------------------------------------------------------------------
// Kernel A: QKV projections via mma.sync bf16 3-term split.
// Epilogue now writes bf16 hi/lo Q,K,V directly (no fp32 QKV).
// ---------------------------------------------------------------------------
#define XPAD 72
#define XHI_OFF 0
#define XLO_OFF (128*XPAD*2)
#define WHI_OFF (2*128*XPAD*2)
#define WLO_OFF (WHI_OFF + 64*XPAD*2)
#define QKV_SMEM (WLO_OFF + 64*XPAD*2)      // 55296 B

__global__ __launch_bounds__(256) void qkv_mma_kernel(
    const float* __restrict__ bq, const float* __restrict__ bk,
    const float* __restrict__ bv)
{
    extern __shared__ char sm[];
    __nv_bfloat16* Xhi_s = (__nv_bfloat16*)(sm + XHI_OFF);
    __nv_bfloat16* Xlo_s = (__nv_bfloat16*)(sm + XLO_OFF);
    __nv_bfloat16* Whi_s = (__nv_bfloat16*)(sm + WHI_OFF);
    __nv_bfloat16* Wlo_s = (__nv_bfloat16*)(sm + WLO_OFF);
    const uint32_t smb = smem_u32(sm);

    const int tid  = threadIdx.x;
    const int lane = tid & 31;
    const int w    = tid >> 5;
    const int m0   = blockIdx.x * 128;
    const int h    = blockIdx.y;
    const int which = blockIdx.z;

    const size_t wbase = ((size_t)which * NH + h) * ND * DH;
    const float* bias = (which == 0) ? bq : (which == 1) ? bk : bv;
    __nv_bfloat16* ohi = (which == 0) ? g_Qhi : (which == 1) ? g_Khi : g_Vhi;
    __nv_bfloat16* olo = (which == 0) ? g_Qlo : (which == 1) ? g_Klo : g_Vlo;

    const int a_row  = w*16 + (lane & 7) + ((lane & 8) ? 8 : 0);
    const int a_kadd = (lane & 16) ? 8 : 0;
    const uint32_t aaddr_hi0 = smb + XHI_OFF + (a_row*XPAD + a_kadd)*2;
    const uint32_t aaddr_lo0 = smb + XLO_OFF + (a_row*XPAD + a_kadd)*2;
    const int b_k    = (lane & 7) + ((lane & 8) ? 8 : 0);
    const int b_nadd = (lane & 16) ? 8 : 0;
    const uint32_t baddr_hi0 = smb + WHI_OFF + (b_k*XPAD + b_nadd)*2;
    const uint32_t baddr_lo0 = smb + WLO_OFF + (b_k*XPAD + b_nadd)*2;

    float c[8][4];
#pragma unroll
    for (int i = 0; i < 8; i++)
#pragma unroll
        for (int j = 0; j < 4; j++) c[i][j] = 0.0f;

    for (int kc = 0; kc < 16; kc++) {
        const int k0 = kc * 64;
        __syncthreads();
#pragma unroll
        for (int i = 0; i < 4; i++) {
            int f = tid + i * 256;
            int r = f >> 3, c8 = (f & 7) * 8;
            *(uint4*)&Xhi_s[r*XPAD + c8] =
                *(const uint4*)&g_Xhi[(size_t)(m0 + r)*ND + k0 + c8];
            *(uint4*)&Xlo_s[r*XPAD + c8] =
                *(const uint4*)&g_Xlo[(size_t)(m0 + r)*ND + k0 + c8];
        }
#pragma unroll
        for (int i = 0; i < 2; i++) {
            int f = tid + i * 256;
            int r = f >> 3, c8 = (f & 7) * 8;
            *(uint4*)&Whi_s[r*XPAD + c8] =
                *(const uint4*)&g_Whi[wbase + (size_t)(k0 + r)*DH + c8];
            *(uint4*)&Wlo_s[r*XPAD + c8] =
                *(const uint4*)&g_Wlo[wbase + (size_t)(k0 + r)*DH + c8];
        }
        __syncthreads();

#pragma unroll
        for (int ks = 0; ks < 4; ks++) {
            uint32_t ahi[4], alo[4];
            ldsm_x4(ahi, aaddr_hi0 + ks*32);
            ldsm_x4(alo, aaddr_lo0 + ks*32);
            const uint32_t bk_off = ks * 16 * XPAD * 2;
#pragma unroll
            for (int nt = 0; nt < 4; nt++) {
                uint32_t bhi[4], blo[4];
                ldsm_x4_t(bhi, baddr_hi0 + bk_off + nt*32);
                ldsm_x4_t(blo, baddr_lo0 + bk_off + nt*32);
                mma16816(c[nt*2],     ahi, bhi[0], bhi[1]);
                mma16816(c[nt*2 + 1], ahi, bhi[2], bhi[3]);
                mma16816(c[nt*2],     ahi, blo[0], blo[1]);
                mma16816(c[nt*2 + 1], ahi, blo[2], blo[3]);
                mma16816(c[nt*2],     alo, bhi[0], bhi[1]);
                mma16816(c[nt*2 + 1], alo, bhi[2], bhi[3]);
            }
        }
    }

    // epilogue: add bias, split to bf16 hi/lo, store
    const int g  = lane >> 2;
    const int tc = (lane & 3) * 2;
    const int mr0 = m0 + w*16 + g;
    const int mr1 = mr0 + 8;
    const size_t r0off = (((size_t)((mr0 >> 11)*NH + h))*NT + (mr0 & (NT-1)))*DH;
    const size_t r1off = (((size_t)((mr1 >> 11)*NH + h))*NT + (mr1 & (NT-1)))*DH;
    const float* bs = bias + h*DH;
#pragma unroll
    for (int nt = 0; nt < 8; nt++) {
        int col = nt*8 + tc;
        float p00 = c[nt][0] + bs[col], p01 = c[nt][1] + bs[col+1];
        float p10 = c[nt][2] + bs[col], p11 = c[nt][3] + bs[col+1];
        uint32_t h0, l0, h1, l1;
        split2(p00, p01, h0, l0);
        split2(p10, p11, h1, l1);
        *(uint32_t*)(ohi + r0off + col) = h0;
        *(uint32_t*)(olo + r0off + col) = l0;
        *(uint32_t*)(ohi + r1off + col) = h1;
        *(uint32_t*)(olo + r1off + col) = l1;
    }
}

// ---------------------------------------------------------------------------
// Kernel B: flash attention via mma.sync bf16 split.
// Block = (b, h, 64-q-tile), 128 threads = 4 warps; warp owns 16 q-rows.
// Smem per 64-key chunk: K^T hi/lo [d=64][kv 64 pad 72], V hi/lo [kv][e pad 72].
// P stays in registers (C->A fragment identity), split hi/lo for AV.
// ---------------------------------------------------------------------------
#define ATM_KTH 0
#define ATM_KTL 9216
#define ATM_VH  18432
#define ATM_VL  27648
#define ATTN_SMEM 36864

__global__ __launch_bounds__(128, 3) void attn_kernel()
{
    extern __shared__ char sb[];
    const uint32_t smb = smem_u32(sb);
    const int tid  = threadIdx.x;
    const int lane = tid & 31;
    const int w    = tid >> 5;
    const int qt   = 31 - blockIdx.x;      // heavy tiles first
    const int h    = blockIdx.y;
    const int b    = blockIdx.z;
    const int q0   = qt * 64;
    const size_t bh = ((size_t)(b*NH + h))*NT;
    const int g   = lane >> 2;
    const int lam = lane & 3;

    // Q fragments (A operand, m16k16 x4 kgroups), hi + lo, loaded once
    uint32_t qhi[4][4], qlo[4][4];
    {
        const __nv_bfloat16* Qh = g_Qhi + (bh + q0 + w*16)*DH;
        const __nv_bfloat16* Ql = g_Qlo + (bh + q0 + w*16)*DH;
#pragma unroll
        for (int kg = 0; kg < 4; kg++) {
            int c0 = kg*16 + 2*lam;
            qhi[kg][0] = *(const uint32_t*)(Qh + g*DH + c0);
            qhi[kg][1] = *(const uint32_t*)(Qh + (g+8)*DH + c0);
            qhi[kg][2] = *(const uint32_t*)(Qh + g*DH + c0 + 8);
            qhi[kg][3] = *(const uint32_t*)(Qh + (g+8)*DH + c0 + 8);
            qlo[kg][0] = *(const uint32_t*)(Ql + g*DH + c0);
            qlo[kg][1] = *(const uint32_t*)(Ql + (g+8)*DH + c0);
            qlo[kg][2] = *(const uint32_t*)(Ql + g*DH + c0 + 8);
            qlo[kg][3] = *(const uint32_t*)(Ql + (g+8)*DH + c0 + 8);
        }
    }

    float m[2]  = { -INFINITY, -INFINITY };
    float lp[2] = { 0.0f, 0.0f };
    float o[8][4];
#pragma unroll
    for (int i = 0; i < 8; i++)
#pragma unroll
        for (int j = 0; j < 4; j++) o[i][j] = 0.0f;

    const unsigned rowb0 = ((unsigned)b << 26)
                         + (unsigned)(h*NT + q0 + w*16 + g) * (unsigned)NT;
    const unsigned rowb1 = rowb0 + 8u*NT;

    // fill-work assignment
    const int farr = tid >> 6;            // 0: hi arrays, 1: lo arrays
    const int fu   = tid & 63;
    const int fjj  = fu & 31;             // kv pair index
    const int fdh  = (fu >> 5) * 32;      // d half
    const __nv_bfloat16* ksrc = farr ? g_Klo : g_Khi;
    char* kdst = sb + (farr ? ATM_KTL : ATM_KTH);
    const __nv_bfloat16* vsrc = farr ? g_Vlo : g_Vhi;
    char* vdst = sb + (farr ? ATM_VL : ATM_VH);
    const int vrow = fu;

    // ldsm base (validated trans-B pattern)
    const uint32_t lrow = (lane & 7) + ((lane & 8) ? 8 : 0);
    const uint32_t lcol = (lane & 16) ? 16 : 0;
    const uint32_t ktb  = smb + lrow*144 + lcol;

    for (int k0 = 0; k0 <= q0; k0 += 64) {
        __syncthreads();
        // ---- fill: K^T (transpose) + V (copy) ----
        {
            const __nv_bfloat16* r0p = ksrc + (bh + k0 + 2*fjj)*DH + fdh;
            const __nv_bfloat16* r1p = r0p + DH;
            __nv_bfloat16 ra[32], rb[32];
#pragma unroll
            for (int i = 0; i < 4; i++) {
                *(uint4*)(ra + i*8) = *(const uint4*)(r0p + i*8);
                *(uint4*)(rb + i*8) = *(const uint4*)(r1p + i*8);
            }
#pragma unroll
            for (int d = 0; d < 32; d++) {
                __nv_bfloat162 pr;
                pr.x = ra[d]; pr.y = rb[d];
                *(__nv_bfloat162*)(kdst + ((fdh + d)*72 + 2*fjj)*2) = pr;
            }
            const __nv_bfloat16* vp = vsrc + (bh + k0 + vrow)*DH;
#pragma unroll
            for (int i = 0; i < 8; i++)
                *(uint4*)(vdst + (vrow*72 + i*8)*2) = *(const uint4*)(vp + i*8);
        }
        __syncthreads();

        // ---- QK^T: s[8 n8-tiles][4], 3-term split ----
        float s[8][4];
#pragma unroll
        for (int i = 0; i < 8; i++)
#pragma unroll
            for (int j = 0; j < 4; j++) s[i][j] = 0.0f;

#pragma unroll
        for (int kg = 0; kg < 4; kg++) {
            uint32_t ka = ktb + kg*2304;          // 16 rows * 144 B
#pragma unroll
            for (int ntp = 0; ntp < 4; ntp++) {
                uint32_t bh4[4], bl4[4];
                ldsm_x4_t(bh4, ka + ATM_KTH + ntp*32);
                ldsm_x4_t(bl4, ka + ATM_KTL + ntp*32);
                mma16816(s[ntp*2],   qhi[kg], bh4[0], bh4[1]);
                mma16816(s[ntp*2+1], qhi[kg], bh4[2], bh4[3]);
                mma16816(s[ntp*2],   qhi[kg], bl4[0], bl4[1]);
                mma16816(s[ntp*2+1], qhi[kg], bl4[2], bl4[3]);
                mma16816(s[ntp*2],   qlo[kg], bh4[0], bh4[1]);
                mma16816(s[ntp*2+1], qlo[kg], bh4[2], bh4[3]);
            }
        }

        // ---- scale + causal mask ----
        const bool diag = (k0 == q0);
#pragma unroll
        for (int nt = 0; nt < 8; nt++)
#pragma unroll
            for (int j = 0; j < 4; j++) {
                float v = s[nt][j] * 0.125f;
                if (diag) {
                    int kv = nt*8 + 2*lam + (j & 1);
                    int qr = w*16 + g + (j >> 1)*8;
                    if (kv > qr) v = -INFINITY;
                }
                s[nt][j] = v;
            }

        // ---- gated bit-exact noise ----
        {
            unsigned kb0 = (unsigned)k0 + 2u*lam;
            float thr0 = m[0] - 20.0f, thr1 = m[1] - 20.0f;
#pragma unroll
            for (int nt = 0; nt < 8; nt++) {
                unsigned kvb = kb0 + nt*8;
                if (s[nt][0] > thr0) s[nt][0] += jax_noise_at(rowb0 + kvb);
                if (s[nt][1] > thr0) s[nt][1] += jax_noise_at(rowb0 + kvb + 1);
                if (s[nt][2] > thr1) s[nt][2] += jax_noise_at(rowb1 + kvb);
                if (s[nt][3] > thr1) s[nt][3] += jax_noise_at(rowb1 + kvb + 1);
            }
        }

        // ---- online softmax (rows g, g+8; quad reduction) ----
        float corr0, corr1;
        {
            float rm0 = -INFINITY, rm1 = -INFINITY;
#pragma unroll
            for (int nt = 0; nt < 8; nt++) {
                rm0 = fmaxf(rm0, fmaxf(s[nt][0], s[nt][1]));
                rm1 = fmaxf(rm1, fmaxf(s[nt][2], s[nt][3]));
            }
            rm0 = fmaxf(rm0, __shfl_xor_sync(0xffffffffu, rm0, 1, 4));
            rm0 = fmaxf(rm0, __shfl_xor_sync(0xffffffffu, rm0, 2, 4));
            rm1 = fmaxf(rm1, __shfl_xor_sync(0xffffffffu, rm1, 1, 4));
            rm1 = fmaxf(rm1, __shfl_xor_sync(0xffffffffu, rm1, 2, 4));
            float mn0 = fmaxf(m[0], rm0);
            float mn1 = fmaxf(m[1], rm1);
            corr0 = __expf(m[0] - mn0);
            corr1 = __expf(m[1] - mn1);
            m[0] = mn0; m[1] = mn1;
            float ps0 = 0.0f, ps1 = 0.0f;
#pragma unroll
            for (int nt = 0; nt < 8; nt++) {
                s[nt][0] = __expf(s[nt][0] - mn0); ps0 += s[nt][0];
                s[nt][1] = __expf(s[nt][1] - mn0); ps0 += s[nt][1];
                s[nt][2] = __expf(s[nt][2] - mn1); ps1 += s[nt][2];
                s[nt][3] = __expf(s[nt][3] - mn1); ps1 += s[nt][3];
            }
            lp[0] = lp[0] * corr0 + ps0;
            lp[1] = lp[1] * corr1 + ps1;
        }
#pragma unroll
        for (int nt = 0; nt < 8; nt++) {
            o[nt][0] *= corr0; o[nt][1] *= corr0;
            o[nt][2] *= corr1; o[nt][3] *= corr1;
        }

        // ---- P: C fragments -> A fragments (bf16 hi/lo), in registers ----
        uint32_t phi[4][4], plo[4][4];
#pragma unroll
        for (int kg = 0; kg < 4; kg++) {
            split2(s[2*kg][0],   s[2*kg][1],   phi[kg][0], plo[kg][0]);
            split2(s[2*kg][2],   s[2*kg][3],   phi[kg][1], plo[kg][1]);
            split2(s[2*kg+1][0], s[2*kg+1][1], phi[kg][2], plo[kg][2]);
            split2(s[2*kg+1][2], s[2*kg+1][3], phi[kg][3], plo[kg][3]);
        }

        // ---- AV: o += P * V, 3-term split ----
#pragma unroll
        for (int kg = 0; kg < 4; kg++) {
            uint32_t va = ktb + ATM_VH + kg*2304;
#pragma unroll
            for (int ntp = 0; ntp < 4; ntp++) {
                uint32_t vh4[4], vl4[4];
                ldsm_x4_t(vh4, va + ntp*32);
                ldsm_x4_t(vl4, va + (ATM_VL - ATM_VH) + ntp*32);
                mma16816(o[ntp*2],   phi[kg], vh4[0], vh4[1]);
                mma16816(o[ntp*2+1], phi[kg], vh4[2], vh4[3]);
                mma16816(o[ntp*2],   phi[kg], vl4[0], vl4[1]);
                mma16816(o[ntp*2+1], phi[kg], vl4[2], vl4[3]);
                mma16816(o[ntp*2],   plo[kg], vh4[0], vh4[1]);
                mma16816(o[ntp*2+1], plo[kg], vh4[2], vh4[3]);
            }
        }
    }

    // ---- finalize ----
    lp[0] += __shfl_xor_sync(0xffffffffu, lp[0], 1, 4);
    lp[0] += __shfl_xor_sync(0xffffffffu, lp[0], 2, 4);
    lp[1] += __shfl_xor_sync(0xffffffffu, lp[1], 1, 4);
    lp[1] += __shfl_xor_sync(0xffffffffu, lp[1], 2, 4);
    const float inv0 = 1.0f / lp[0];
    const float inv1 = 1.0f / lp[1];
    const size_t z0 = (bh + q0 + w*16 + g)*DH;
    const size_t z1 = z0 + 8*DH;
#pragma unroll
    for (int nt = 0; nt < 8; nt++) {
        int col = nt*8 + 2*lam;
        *(float2*)(g_Z + z0 + col) = make_float2(o[nt][0]*inv0, o[nt][1]*inv0);
        *(float2*)(g_Z + z1 + col) = make_float2(o[nt][2]*inv1, o[nt][3]*inv1);
    }
}

// ---------------------------------------------------------------------------
// Kernel C: output projection. 128x64 tile, 256 threads, 4m x 8n micro-tile.
// [unchanged — passing]
// ---------------------------------------------------------------------------
__global__ __launch_bounds__(256) void oproj_kernel(
    const float* __restrict__ Wo, const float* __restrict__ bo,
    float* __restrict__ out)
{
    __shared__ float Zs[128][36];
    __shared__ float Ws[32][64];

    const int m0 = blockIdx.x * 128;
    const int n0 = blockIdx.y * 64;
    const int tid = threadIdx.x;
    const int tx = tid & 7;
    const int ty = tid >> 3;

    u64 c2[4][4];
#pragma unroll
    for (int i = 0; i < 4; i++)
#pragma unroll
        for (int j = 0; j < 4; j++) c2[i][j] = 0ull;

    for (int k0 = 0; k0 < NH*DH; k0 += 32) {
        const int hh = k0 >> 6;
        const int e0 = k0 & 63;
        __syncthreads();
#pragma unroll
        for (int i = 0; i < 4; i++) {
            int f = tid + i * 256;
            int r = f >> 3, c4 = (f & 7) * 4;
            int n = m0 + r;
            int bb = n >> 11;
            int t  = n & (NT - 1);
            *(float4*)&Zs[r][c4] =
                *(const float4*)(g_Z + (((size_t)(bb*NH + hh))*NT + t)*DH + e0 + c4);
        }
#pragma unroll
        for (int i = 0; i < 2; i++) {
            int f = tid + i * 256;
            int r = f >> 4, c4 = (f & 15) * 4;
            *(float4*)&Ws[r][c4] = *(const float4*)(Wo + (size_t)(k0 + r)*ND + n0 + c4);
        }
        __syncthreads();
#pragma unroll 8
        for (int kk = 0; kk < 32; kk++) {
            ulonglong2 bA = *(const ulonglong2*)&Ws[kk][tx*4];
            ulonglong2 bB = *(const ulonglong2*)&Ws[kk][32 + tx*4];
#pragma unroll
            for (int i = 0; i < 4; i++) {
                float av = Zs[ty*4 + i][kk];
                u64 ai = pack2(av, av);
                c2[i][0] = fma2(ai, bA.x, c2[i][0]);
                c2[i][1] = fma2(ai, bA.y, c2[i][1]);
                c2[i][2] = fma2(ai, bB.x, c2[i][2]);
                c2[i][3] = fma2(ai, bB.y, c2[i][3]);
            }
        }
    }

    float4 boA = *(const float4*)(bo + n0 + tx*4);
    float4 boB = *(const float4*)(bo + n0 + 32 + tx*4);
#pragma unroll
    for (int i = 0; i < 4; i++) {
        int n = m0 + ty*4 + i;
        float* orow = out + (size_t)n*ND + n0;
        float4 rA, rB;
        unpack2(c2[i][0], rA.x, rA.y);
        unpack2(c2[i][1], rA.z, rA.w);
        unpack2(c2[i][2], rB.x, rB.y);
        unpack2(c2[i][3], rB.z, rB.w);
        rA.x += boA.x; rA.y += boA.y; rA.z += boA.z; rA.w += boA.w;
        rB.x += boB.x; rB.y += boB.y; rB.z += boB.z; rB.w += boB.w;
        *(float4*)(orow + tx*4)      = rA;
        *(float4*)(orow + 32 + tx*4) = rB;
    }
}

// ---------------------------------------------------------------------------
extern "C" void kernel_launch(void* const* d_in, const int* in_sizes, int n_in,
                              void* d_out, int out_size)
{
    (void)in_sizes; (void)n_in; (void)out_size;
    const float* X  = (const float*)d_in[0];
    const float* Wq = (const float*)d_in[1];
    const float* Wk = (const float*)d_in[2];
    const float* Wv = (const float*)d_in[3];
    const float* Wo = (const float*)d_in[4];
    const float* bq = (const float*)d_in[5];
    const float* bk = (const float*)d_in[6];
    const float* bv = (const float*)d_in[7];
    const float* bo = (const float*)d_in[8];
    float* out = (float*)d_out;

    static int configured = 0;
    if (!configured) {
        cudaFuncSetAttribute(qkv_mma_kernel,
                             cudaFuncAttributeMaxDynamicSharedMemorySize, QKV_SMEM);
        cudaFuncSetAttribute(attn_kernel,
                             cudaFuncAttributeMaxDynamicSharedMemorySize, ATTN_SMEM);
        configured = 1;
    }

    split_x_kernel<<<NB*NT*ND/1024, 256>>>(X);
    split_w_kernel<<<dim3(NH*ND*DH/1024, 3), 256>>>(Wq, Wk, Wv);
    qkv_mma_kernel<<<dim3(32, 16, 3), 256, QKV_SMEM>>>(bq, bk, bv);
    attn_kernel<<<dim3(32, 16, 2), 128, ATTN_SMEM>>>();
    oproj_kernel<<<dim3(32, 16), 256>>>(Wo, bo, out);
}

// round 17
// speedup vs baseline: 2.1417x; 1.2856x over previous
#include <cuda_runtime.h>
#include <cuda_bf16.h>
#include <cstdint>
#include <math.h>

#define NB 2
#define NH 16
#define NT 2048
#define ND 1024
#define DH 64

typedef unsigned long long u64;

// Scratch (allocation-free), all bf16 hi/lo pairs.
__device__ __nv_bfloat16 g_Qhi[NB*NH*NT*DH];
__device__ __nv_bfloat16 g_Qlo[NB*NH*NT*DH];
__device__ __nv_bfloat16 g_Khi[NB*NH*NT*DH];
__device__ __nv_bfloat16 g_Klo[NB*NH*NT*DH];
__device__ __nv_bfloat16 g_Vhi[NB*NH*NT*DH];
__device__ __nv_bfloat16 g_Vlo[NB*NH*NT*DH];
__device__ __nv_bfloat16 g_Zhi[NB*NH*NT*DH];
__device__ __nv_bfloat16 g_Zlo[NB*NH*NT*DH];
__device__ __nv_bfloat16 g_Xhi[NB*NT*ND];
__device__ __nv_bfloat16 g_Xlo[NB*NT*ND];
__device__ __nv_bfloat16 g_Whi[3*NH*ND*DH];
__device__ __nv_bfloat16 g_Wlo[3*NH*ND*DH];
__device__ __nv_bfloat16 g_Wohi[NH*DH*ND];
__device__ __nv_bfloat16 g_Wolo[NH*DH*ND];

// ---------------------------------------------------------------------------
// mma.sync / ldmatrix / cp.async helpers (sm_80 baseline — works on compute_103)
// ---------------------------------------------------------------------------
__device__ __forceinline__ uint32_t smem_u32(const void* p)
{
    uint32_t a;
    asm("{ .reg .u64 t; cvta.to.shared.u64 t, %1; cvt.u32.u64 %0, t; }"
        : "=r"(a) : "l"(p));
    return a;
}

__device__ __forceinline__ void ldsm_x4(uint32_t* r, uint32_t a)
{
    asm volatile("ldmatrix.sync.aligned.m8n8.x4.shared.b16 {%0,%1,%2,%3}, [%4];"
                 : "=r"(r[0]), "=r"(r[1]), "=r"(r[2]), "=r"(r[3]) : "r"(a));
}

__device__ __forceinline__ void ldsm_x4_t(uint32_t* r, uint32_t a)
{
    asm volatile("ldmatrix.sync.aligned.m8n8.x4.trans.shared.b16 {%0,%1,%2,%3}, [%4];"
                 : "=r"(r[0]), "=r"(r[1]), "=r"(r[2]), "=r"(r[3]) : "r"(a));
}

__device__ __forceinline__ void mma16816(float* c, const uint32_t* a,
                                         uint32_t b0, uint32_t b1)
{
    asm volatile(
        "mma.sync.aligned.m16n8k16.row.col.f32.bf16.bf16.f32 "
        "{%0,%1,%2,%3},{%4,%5,%6,%7},{%8,%9},{%0,%1,%2,%3};"
        : "+f"(c[0]), "+f"(c[1]), "+f"(c[2]), "+f"(c[3])
        : "r"(a[0]), "r"(a[1]), "r"(a[2]), "r"(a[3]), "r"(b0), "r"(b1));
}

__device__ __forceinline__ void cp16(uint32_t d, const void* s)
{
    asm volatile("cp.async.cg.shared.global [%0], [%1], 16;"
                 :: "r"(d), "l"(s) : "memory");
}

// split two fp32 into packed bf16 hi pair + lo-residual pair
__device__ __forceinline__ void split2(float x, float y, uint32_t& hi, uint32_t& lo)
{
    __nv_bfloat162 h = __floats2bfloat162_rn(x, y);
    __nv_bfloat162 l = __floats2bfloat162_rn(x - __bfloat162float(h.x),
                                             y - __bfloat162float(h.y));
    hi = *(uint32_t*)&h;
    lo = *(uint32_t*)&l;
}

// ---------------------------------------------------------------------------
// JAX threefry2x32 with key (0, 42)
// ---------------------------------------------------------------------------
__device__ __forceinline__ void threefry_0_42(unsigned x0, unsigned x1,
                                              unsigned &o0, unsigned &o1)
{
    const unsigned ks0 = 0u;
    const unsigned ks1 = 42u;
    const unsigned ks2 = 0x1BD11BDAu ^ 42u;
    x0 += ks0; x1 += ks1;
#define TF_R(r) do { x0 += x1; x1 = __funnelshift_l(x1, x1, (r)); x1 ^= x0; } while (0)
    TF_R(13); TF_R(15); TF_R(26); TF_R(6);
    x0 += ks1; x1 += ks2 + 1u;
    TF_R(17); TF_R(29); TF_R(16); TF_R(24);
    x0 += ks2; x1 += ks0 + 2u;
    TF_R(13); TF_R(15); TF_R(26); TF_R(6);
    x0 += ks0; x1 += ks1 + 3u;
    TF_R(17); TF_R(29); TF_R(16); TF_R(24);
    x0 += ks1; x1 += ks2 + 4u;
    TF_R(13); TF_R(15); TF_R(26); TF_R(6);
    x0 += ks2; x1 += ks0 + 5u;
#undef TF_R
    o0 = x0; o1 = x1;
}

__device__ __forceinline__ float noise_from_bits(unsigned bits)
{
    float u = __uint_as_float((bits >> 9) | 0x3f800000u) - 1.0f;   // [0,1)
    const float lo = -0.99999994f;                                 // nextafter(-1,0)
    float v = fmaf(u, 2.0f, lo);
    v = fmaxf(v, lo);
    return 1.4142135623730951f * erfinvf(v) * 0.01f;
}

// JAX partitionable threefry: counter (0, flat_idx); draw = out0 ^ out1
__device__ __noinline__ float jax_noise_at(unsigned flat_idx)
{
    unsigned o0, o1;
    threefry_0_42(0u, flat_idx, o0, o1);
    return noise_from_bits(o0 ^ o1);
}

// ---------------------------------------------------------------------------
// Split kernels: fp32 -> bf16 hi + lo residual.
// ---------------------------------------------------------------------------
__device__ __forceinline__ void split4(float4 v, __nv_bfloat162& h0, __nv_bfloat162& h1,
                                       __nv_bfloat162& l0, __nv_bfloat162& l1)
{
    h0 = __floats2bfloat162_rn(v.x, v.y);
    h1 = __floats2bfloat162_rn(v.z, v.w);
    l0 = __floats2bfloat162_rn(v.x - __bfloat162float(h0.x),
                               v.y - __bfloat162float(h0.y));
    l1 = __floats2bfloat162_rn(v.z - __bfloat162float(h1.x),
                               v.w - __bfloat162float(h1.y));
}

__global__ __launch_bounds__(256) void split_x_kernel(const float* __restrict__ X)
{
    int i = (blockIdx.x * 256 + threadIdx.x) * 4;
    float4 v = *(const float4*)(X + i);
    __nv_bfloat162 h0, h1, l0, l1;
    split4(v, h0, h1, l0, l1);
    *(__nv_bfloat162*)(g_Xhi + i)     = h0;
    *(__nv_bfloat162*)(g_Xhi + i + 2) = h1;
    *(__nv_bfloat162*)(g_Xlo + i)     = l0;
    *(__nv_bfloat162*)(g_Xlo + i + 2) = l1;
}

__global__ __launch_bounds__(256) void split_w_kernel(
    const float* __restrict__ Wq, const float* __restrict__ Wk,
    const float* __restrict__ Wv)
{
    const float* W = (blockIdx.y == 0) ? Wq : (blockIdx.y == 1) ? Wk : Wv;
    size_t base = (size_t)blockIdx.y * NH * ND * DH;
    int i = (blockIdx.x * 256 + threadIdx.x) * 4;
    float4 v = *(const float4*)(W + i);
    __nv_bfloat162 h0, h1, l0, l1;
    split4(v, h0, h1, l0, l1);
    *(__nv_bfloat162*)(g_Whi + base + i)     = h0;
    *(__nv_bfloat162*)(g_Whi + base + i + 2) = h1;
    *(__nv_bfloat162*)(g_Wlo + base + i)     = l0;
    *(__nv_bfloat162*)(g_Wlo + base + i + 2) = l1;
}

__global__ __launch_bounds__(256) void split_wo_kernel(const float* __restrict__ Wo)
{
    int i = (blockIdx.x * 256 + threadIdx.x) * 4;
    float4 v = *(const float4*)(Wo + i);
    __nv_bfloat162 h0, h1, l0, l1;
    split4(v, h0, h1, l0, l1);
    *(__nv_bfloat162*)(g_Wohi + i)     = h0;
    *(__nv_bfloat162*)(g_Wohi + i + 2) = h1;
    *(__nv_bfloat162*)(g_Wolo + i)     = l0;
    *(__nv_bfloat162*)(g_Wolo + i + 2) = l1;
}

// ---------------------------------------------------------------------------
// Kernel A: QKV projections via mma.sync bf16 3-term split. [validated]
// Epilogue writes bf16 hi/lo Q,K,V directly.
// ---------------------------------------------------------------------------
#define XPAD 72
#define XHI_OFF 0
#define XLO_OFF (128*XPAD*2)
#define WHI_OFF (2*128*XPAD*2)
#define WLO_OFF (WHI_OFF + 64*XPAD*2)
#define QKV_SMEM (WLO_OFF + 64*XPAD*2)      // 55296 B

__global__ __launch_bounds__(256) void qkv_mma_kernel(
    const float* __restrict__ bq, const float* __restrict__ bk,
    const float* __restrict__ bv)
{
    extern __shared__ char sm[];
    __nv_bfloat16* Xhi_s = (__nv_bfloat16*)(sm + XHI_OFF);
    __nv_bfloat16* Xlo_s = (__nv_bfloat16*)(sm + XLO_OFF);
    __nv_bfloat16* Whi_s = (__nv_bfloat16*)(sm + WHI_OFF);
    __nv_bfloat16* Wlo_s = (__nv_bfloat16*)(sm + WLO_OFF);
    const uint32_t smb = smem_u32(sm);

    const int tid  = threadIdx.x;
    const int lane = tid & 31;
    const int w    = tid >> 5;
    const int m0   = blockIdx.x * 128;
    const int h    = blockIdx.y;
    const int which = blockIdx.z;

    const size_t wbase = ((size_t)which * NH + h) * ND * DH;
    const float* bias = (which == 0) ? bq : (which == 1) ? bk : bv;
    __nv_bfloat16* ohi = (which == 0) ? g_Qhi : (which == 1) ? g_Khi : g_Vhi;
    __nv_bfloat16* olo = (which == 0) ? g_Qlo : (which == 1) ? g_Klo : g_Vlo;

    const int a_row  = w*16 + (lane & 7) + ((lane & 8) ? 8 : 0);
    const int a_kadd = (lane & 16) ? 8 : 0;
    const uint32_t aaddr_hi0 = smb + XHI_OFF + (a_row*XPAD + a_kadd)*2;
    const uint32_t aaddr_lo0 = smb + XLO_OFF + (a_row*XPAD + a_kadd)*2;
    const int b_k    = (lane & 7) + ((lane & 8) ? 8 : 0);
    const int b_nadd = (lane & 16) ? 8 : 0;
    const uint32_t baddr_hi0 = smb + WHI_OFF + (b_k*XPAD + b_nadd)*2;
    const uint32_t baddr_lo0 = smb + WLO_OFF + (b_k*XPAD + b_nadd)*2;

    float c[8][4];
#pragma unroll
    for (int i = 0; i < 8; i++)
#pragma unroll
        for (int j = 0; j < 4; j++) c[i][j] = 0.0f;

    for (int kc = 0; kc < 16; kc++) {
        const int k0 = kc * 64;
        __syncthreads();
#pragma unroll
        for (int i = 0; i < 4; i++) {
            int f = tid + i * 256;
            int r = f >> 3, c8 = (f & 7) * 8;
            *(uint4*)&Xhi_s[r*XPAD + c8] =
                *(const uint4*)&g_Xhi[(size_t)(m0 + r)*ND + k0 + c8];
            *(uint4*)&Xlo_s[r*XPAD + c8] =
                *(const uint4*)&g_Xlo[(size_t)(m0 + r)*ND + k0 + c8];
        }
#pragma unroll
        for (int i = 0; i < 2; i++) {
            int f = tid + i * 256;
            int r = f >> 3, c8 = (f & 7) * 8;
            *(uint4*)&Whi_s[r*XPAD + c8] =
                *(const uint4*)&g_Whi[wbase + (size_t)(k0 + r)*DH + c8];
            *(uint4*)&Wlo_s[r*XPAD + c8] =
                *(const uint4*)&g_Wlo[wbase + (size_t)(k0 + r)*DH + c8];
        }
        __syncthreads();

#pragma unroll
        for (int ks = 0; ks < 4; ks++) {
            uint32_t ahi[4], alo[4];
            ldsm_x4(ahi, aaddr_hi0 + ks*32);
            ldsm_x4(alo, aaddr_lo0 + ks*32);
            const uint32_t bk_off = ks * 16 * XPAD * 2;
#pragma unroll
            for (int nt = 0; nt < 4; nt++) {
                uint32_t bhi[4], blo[4];
                ldsm_x4_t(bhi, baddr_hi0 + bk_off + nt*32);
                ldsm_x4_t(blo, baddr_lo0 + bk_off + nt*32);
                mma16816(c[nt*2],     ahi, bhi[0], bhi[1]);
                mma16816(c[nt*2 + 1], ahi, bhi[2], bhi[3]);
                mma16816(c[nt*2],     ahi, blo[0], blo[1]);
                mma16816(c[nt*2 + 1], ahi, blo[2], blo[3]);
                mma16816(c[nt*2],     alo, bhi[0], bhi[1]);
                mma16816(c[nt*2 + 1], alo, bhi[2], bhi[3]);
            }
        }
    }

    const int g  = lane >> 2;
    const int tc = (lane & 3) * 2;
    const int mr0 = m0 + w*16 + g;
    const int mr1 = mr0 + 8;
    const size_t r0off = (((size_t)((mr0 >> 11)*NH + h))*NT + (mr0 & (NT-1)))*DH;
    const size_t r1off = (((size_t)((mr1 >> 11)*NH + h))*NT + (mr1 & (NT-1)))*DH;
    const float* bs = bias + h*DH;
#pragma unroll
    for (int nt = 0; nt < 8; nt++) {
        int col = nt*8 + tc;
        float p00 = c[nt][0] + bs[col], p01 = c[nt][1] + bs[col+1];
        float p10 = c[nt][2] + bs[col], p11 = c[nt][3] + bs[col+1];
        uint32_t h0, l0, h1, l1;
        split2(p00, p01, h0, l0);
        split2(p10, p11, h1, l1);
        *(uint32_t*)(ohi + r0off + col) = h0;
        *(uint32_t*)(olo + r0off + col) = l0;
        *(uint32_t*)(ohi + r1off + col) = h1;
        *(uint32_t*)(olo + r1off + col) = l1;
    }
}

// ---------------------------------------------------------------------------
// Kernel B: flash attention via mma.sync bf16 split, cp.async double-buffered.
// Block = (b, h, 64-q-tile), 128 threads = 4 warps; warp owns 16 q-rows.
// K and V both stored NATURAL [kv][d]/[kv][e] (pad 72). QK B-operand via
// NON-trans ldmatrix; V via trans ldmatrix. P stays in registers.
// Buffer: {Khi 0, Klo 9216, Vhi 18432, Vlo 27648}, x2 buffers.
// ---------------------------------------------------------------------------
#define BUFSZ 36864
#define ATTN_SMEM (2*BUFSZ)

#define ATTN_PREFETCH(cc) do {                                                \
    const int _k0 = (cc)*64;                                                  \
    const uint32_t _db = smb + ((cc)&1)*BUFSZ;                                \
    _Pragma("unroll")                                                         \
    for (int ii = 0; ii < 4; ii++) {                                          \
        const int _row = ii*16 + rr;                                          \
        const uint32_t _do = _db + _row*144 + seg*16;                         \
        const size_t _so = (bh + _k0 + _row)*DH + seg*8;                      \
        cp16(_do,         g_Khi + _so);                                       \
        cp16(_do +  9216, g_Klo + _so);                                       \
        cp16(_do + 18432, g_Vhi + _so);                                       \
        cp16(_do + 27648, g_Vlo + _so);                                       \
    }                                                                         \
    asm volatile("cp.async.commit_group;" ::: "memory");                      \
} while (0)

__global__ __launch_bounds__(128, 3) void attn_kernel()
{
    extern __shared__ char sb[];
    const uint32_t smb = smem_u32(sb);
    const int tid  = threadIdx.x;
    const int lane = tid & 31;
    const int w    = tid >> 5;
    const int qt   = 31 - blockIdx.x;      // heavy tiles first
    const int h    = blockIdx.y;
    const int b    = blockIdx.z;
    const int q0   = qt * 64;
    const size_t bh = ((size_t)(b*NH + h))*NT;
    const int g   = lane >> 2;
    const int lam = lane & 3;
    const int rr  = tid >> 3;              // prefetch row group
    const int seg = tid & 7;               // prefetch 16B segment

    // Q fragments (A operand, m16k16 x4 kgroups), hi + lo, loaded once
    uint32_t qhi[4][4], qlo[4][4];
    {
        const __nv_bfloat16* Qh = g_Qhi + (bh + q0 + w*16)*DH;
        const __nv_bfloat16* Ql = g_Qlo + (bh + q0 + w*16)*DH;
#pragma unroll
        for (int kg = 0; kg < 4; kg++) {
            int c0 = kg*16 + 2*lam;
            qhi[kg][0] = *(const uint32_t*)(Qh + g*DH + c0);
            qhi[kg][1] = *(const uint32_t*)(Qh + (g+8)*DH + c0);
            qhi[kg][2] = *(const uint32_t*)(Qh + g*DH + c0 + 8);
            qhi[kg][3] = *(const uint32_t*)(Qh + (g+8)*DH + c0 + 8);
            qlo[kg][0] = *(const uint32_t*)(Ql + g*DH + c0);
            qlo[kg][1] = *(const uint32_t*)(Ql + (g+8)*DH + c0);
            qlo[kg][2] = *(const uint32_t*)(Ql + g*DH + c0 + 8);
            qlo[kg][3] = *(const uint32_t*)(Ql + (g+8)*DH + c0 + 8);
        }
    }

    float m[2]  = { -INFINITY, -INFINITY };
    float lp[2] = { 0.0f, 0.0f };
    float o[8][4];
#pragma unroll
    for (int i = 0; i < 8; i++)
#pragma unroll
        for (int j = 0; j < 4; j++) o[i][j] = 0.0f;

    const unsigned rowb0 = ((unsigned)b << 26)
                         + (unsigned)(h*NT + q0 + w*16 + g) * (unsigned)NT;
    const unsigned rowb1 = rowb0 + 8u*NT;

    // K B-frag base (non-trans): lanes 0-7 n0-7@k0, 8-15 n0-7@k+8,
    // 16-23 n8-15@k0, 24-31 n8-15@k+8
    const uint32_t nrow  = (lane & 7) + ((lane & 16) ? 8 : 0);
    const uint32_t koff2 = (lane & 8) ? 16 : 0;
    const uint32_t kfo   = nrow*144 + koff2;
    // V B-frag base (trans): rows = kv (lane&15), col offset by lane&16
    const uint32_t vfo   = 18432 + (lane & 15)*144 + ((lane & 16) ? 16 : 0);

    const int nch = qt + 1;
    ATTN_PREFETCH(0);

    for (int c = 0; c < nch; c++) {
        if (c + 1 < nch) {
            ATTN_PREFETCH(c + 1);
            asm volatile("cp.async.wait_group 1;" ::: "memory");
        } else {
            asm volatile("cp.async.wait_group 0;" ::: "memory");
        }
        __syncthreads();
        const int k0 = c*64;
        const uint32_t buf = smb + (c&1)*BUFSZ;
        const uint32_t kB = buf + kfo;
        const uint32_t vB = buf + vfo;

        // ---- QK^T: s[8 n8-tiles][4], 3-term split ----
        float s[8][4];
#pragma unroll
        for (int i = 0; i < 8; i++)
#pragma unroll
            for (int j = 0; j < 4; j++) s[i][j] = 0.0f;

#pragma unroll
        for (int kg = 0; kg < 4; kg++) {
#pragma unroll
            for (int ntp = 0; ntp < 4; ntp++) {
                uint32_t bh4[4], bl4[4];
                uint32_t ad = kB + ntp*2304 + kg*32;
                ldsm_x4(bh4, ad);
                ldsm_x4(bl4, ad + 9216);
                mma16816(s[ntp*2],   qhi[kg], bh4[0], bh4[1]);
                mma16816(s[ntp*2+1], qhi[kg], bh4[2], bh4[3]);
                mma16816(s[ntp*2],   qhi[kg], bl4[0], bl4[1]);
                mma16816(s[ntp*2+1], qhi[kg], bl4[2], bl4[3]);
                mma16816(s[ntp*2],   qlo[kg], bh4[0], bh4[1]);
                mma16816(s[ntp*2+1], qlo[kg], bh4[2], bh4[3]);
            }
        }

        // ---- scale + causal mask ----
        const bool diag = (k0 == q0);
#pragma unroll
        for (int nt = 0; nt < 8; nt++)
#pragma unroll
            for (int j = 0; j < 4; j++) {
                float v = s[nt][j] * 0.125f;
                if (diag) {
                    int kv = nt*8 + 2*lam + (j & 1);
                    int qr = w*16 + g + (j >> 1)*8;
                    if (kv > qr) v = -INFINITY;
                }
                s[nt][j] = v;
            }

        // ---- pre-noise chunk max (for gating) ----
        float em0 = m[0], em1 = m[1];
#pragma unroll
        for (int nt = 0; nt < 8; nt++) {
            em0 = fmaxf(em0, fmaxf(s[nt][0], s[nt][1]));
            em1 = fmaxf(em1, fmaxf(s[nt][2], s[nt][3]));
        }
        em0 = fmaxf(em0, __shfl_xor_sync(0xffffffffu, em0, 1, 4));
        em0 = fmaxf(em0, __shfl_xor_sync(0xffffffffu, em0, 2, 4));
        em1 = fmaxf(em1, __shfl_xor_sync(0xffffffffu, em1, 1, 4));
        em1 = fmaxf(em1, __shfl_xor_sync(0xffffffffu, em1, 2, 4));

        // ---- gated bit-exact noise (skip iff p < ~2e-9; |noise|<0.06) ----
        {
            const float thr0 = em0 - 20.125f;
            const float thr1 = em1 - 20.125f;
            unsigned kb0 = (unsigned)k0 + 2u*lam;
#pragma unroll
            for (int nt = 0; nt < 8; nt++) {
                unsigned kvb = kb0 + nt*8;
                if (s[nt][0] > thr0) s[nt][0] += jax_noise_at(rowb0 + kvb);
                if (s[nt][1] > thr0) s[nt][1] += jax_noise_at(rowb0 + kvb + 1);
                if (s[nt][2] > thr1) s[nt][2] += jax_noise_at(rowb1 + kvb);
                if (s[nt][3] > thr1) s[nt][3] += jax_noise_at(rowb1 + kvb + 1);
            }
        }

        // ---- online softmax (exact post-noise max) ----
        float corr0, corr1;
        {
            float rm0 = -INFINITY, rm1 = -INFINITY;
#pragma unroll
            for (int nt = 0; nt < 8; nt++) {
                rm0 = fmaxf(rm0, fmaxf(s[nt][0], s[nt][1]));
                rm1 = fmaxf(rm1, fmaxf(s[nt][2], s[nt][3]));
            }
            rm0 = fmaxf(rm0, __shfl_xor_sync(0xffffffffu, rm0, 1, 4));
            rm0 = fmaxf(rm0, __shfl_xor_sync(0xffffffffu, rm0, 2, 4));
            rm1 = fmaxf(rm1, __shfl_xor_sync(0xffffffffu, rm1, 1, 4));
            rm1 = fmaxf(rm1, __shfl_xor_sync(0xffffffffu, rm1, 2, 4));
            float mn0 = fmaxf(m[0], rm0);
            float mn1 = fmaxf(m[1], rm1);
            corr0 = __expf(m[0] - mn0);
            corr1 = __expf(m[1] - mn1);
            m[0] = mn0; m[1] = mn1;
            float ps0 = 0.0f, ps1 = 0.0f;
#pragma unroll
            for (int nt = 0; nt < 8; nt++) {
                s[nt][0] = __expf(s[nt][0] - mn0); ps0 += s[nt][0];
                s[nt][1] = __expf(s[nt][1] - mn0); ps0 += s[nt][1];
                s[nt][2] = __expf(s[nt][2] - mn1); ps1 += s[nt][2];
                s[nt][3] = __expf(s[nt][3] - mn1); ps1 += s[nt][3];
            }
            lp[0] = lp[0] * corr0 + ps0;
            lp[1] = lp[1] * corr1 + ps1;
        }
#pragma unroll
        for (int nt = 0; nt < 8; nt++) {
            o[nt][0] *= corr0; o[nt][1] *= corr0;
            o[nt][2] *= corr1; o[nt][3] *= corr1;
        }

        // ---- P: C fragments -> A fragments (bf16 hi/lo), in registers ----
        uint32_t phi[4][4], plo[4][4];
#pragma unroll
        for (int kg = 0; kg < 4; kg++) {
            split2(s[2*kg][0],   s[2*kg][1],   phi[kg][0], plo[kg][0]);
            split2(s[2*kg][2],   s[2*kg][3],   phi[kg][1], plo[kg][1]);
            split2(s[2*kg+1][0], s[2*kg+1][1], phi[kg][2], plo[kg][2]);
            split2(s[2*kg+1][2], s[2*kg+1][3], phi[kg][3], plo[kg][3]);
        }

        // ---- AV: o += P * V, 3-term split (V via trans ldsm) ----
#pragma unroll
        for (int kg = 0; kg < 4; kg++) {
            uint32_t va = vB + kg*2304;
#pragma unroll
            for (int ntp = 0; ntp < 4; ntp++) {
                uint32_t vh4[4], vl4[4];
                ldsm_x4_t(vh4, va + ntp*32);
                ldsm_x4_t(vl4, va + 9216 + ntp*32);
                mma16816(o[ntp*2],   phi[kg], vh4[0], vh4[1]);
                mma16816(o[ntp*2+1], phi[kg], vh4[2], vh4[3]);
                mma16816(o[ntp*2],   phi[kg], vl4[0], vl4[1]);
                mma16816(o[ntp*2+1], phi[kg], vl4[2], vl4[3]);
                mma16816(o[ntp*2],   plo[kg], vh4[0], vh4[1]);
                mma16816(o[ntp*2+1], plo[kg], vh4[2], vh4[3]);
            }
        }
        __syncthreads();
    }

    // ---- finalize: split Z to bf16 hi/lo for the mma oproj ----
    lp[0] += __shfl_xor_sync(0xffffffffu, lp[0], 1, 4);
    lp[0] += __shfl_xor_sync(0xffffffffu, lp[0], 2, 4);
    lp[1] += __shfl_xor_sync(0xffffffffu, lp[1], 1, 4);
    lp[1] += __shfl_xor_sync(0xffffffffu, lp[1], 2, 4);
    const float inv0 = 1.0f / lp[0];
    const float inv1 = 1.0f / lp[1];
    const size_t z0 = (bh + q0 + w*16 + g)*DH;
    const size_t z1 = z0 + 8*DH;
#pragma unroll
    for (int nt = 0; nt < 8; nt++) {
        int col = nt*8 + 2*lam;
        uint32_t h0, l0, h1, l1;
        split2(o[nt][0]*inv0, o[nt][1]*inv0, h0, l0);
        split2(o[nt][2]*inv1, o[nt][3]*inv1, h1, l1);
        *(uint32_t*)(g_Zhi + z0 + col) = h0;
        *(uint32_t*)(g_Zlo + z0 + col) = l0;
        *(uint32_t*)(g_Zhi + z1 + col) = h1;
        *(uint32_t*)(g_Zlo + z1 + col) = l1;
    }
}

// ---------------------------------------------------------------------------
// Kernel C: output projection via mma.sync bf16 3-term split (qkv clone).
// grid (32 mtiles, 16 ntiles), 256 threads; chunks kc = head index.
// ---------------------------------------------------------------------------
__global__ __launch_bounds__(256) void oproj_mma_kernel(
    const float* __restrict__ bo, float* __restrict__ out)
{
    extern __shared__ char sm[];
    __nv_bfloat16* Xhi_s = (__nv_bfloat16*)(sm + XHI_OFF);
    __nv_bfloat16* Xlo_s = (__nv_bfloat16*)(sm + XLO_OFF);
    __nv_bfloat16* Whi_s = (__nv_bfloat16*)(sm + WHI_OFF);
    __nv_bfloat16* Wlo_s = (__nv_bfloat16*)(sm + WLO_OFF);
    const uint32_t smb = smem_u32(sm);

    const int tid  = threadIdx.x;
    const int lane = tid & 31;
    const int w    = tid >> 5;
    const int m0   = blockIdx.x * 128;
    const int n0   = blockIdx.y * 64;

    const int a_row  = w*16 + (lane & 7) + ((lane & 8) ? 8 : 0);
    const int a_kadd = (lane & 16) ? 8 : 0;
    const uint32_t aaddr_hi0 = smb + XHI_OFF + (a_row*XPAD + a_kadd)*2;
    const uint32_t aaddr_lo0 = smb + XLO_OFF + (a_row*XPAD + a_kadd)*2;
    const int b_k    = (lane & 7) + ((lane & 8) ? 8 : 0);
    const int b_nadd = (lane & 16) ? 8 : 0;
    const uint32_t baddr_hi0 = smb + WHI_OFF + (b_k*XPAD + b_nadd)*2;
    const uint32_t baddr_lo0 = smb + WLO_OFF + (b_k*XPAD + b_nadd)*2;

    float c[8][4];
#pragma unroll
    for (int i = 0; i < 8; i++)
#pragma unroll
        for (int j = 0; j < 4; j++) c[i][j] = 0.0f;

    for (int kc = 0; kc < 16; kc++) {
        __syncthreads();
        // A tile: Z rows m0..+127, head kc, 64 e-cols
#pragma unroll
        for (int i = 0; i < 4; i++) {
            int f = tid + i * 256;
            int r = f >> 3, c8 = (f & 7) * 8;
            int n = m0 + r;
            int bb = n >> 11;
            int t  = n & (NT - 1);
            size_t src = (((size_t)(bb*NH + kc))*NT + t)*DH + c8;
            *(uint4*)&Xhi_s[r*XPAD + c8] = *(const uint4*)&g_Zhi[src];
            *(uint4*)&Xlo_s[r*XPAD + c8] = *(const uint4*)&g_Zlo[src];
        }
        // B tile: Wo rows (kc,e 0..63) x cols n0..+63
#pragma unroll
        for (int i = 0; i < 2; i++) {
            int f = tid + i * 256;
            int r = f >> 3, c8 = (f & 7) * 8;
            size_t src = (size_t)(kc*64 + r)*ND + n0 + c8;
            *(uint4*)&Whi_s[r*XPAD + c8] = *(const uint4*)&g_Wohi[src];
            *(uint4*)&Wlo_s[r*XPAD + c8] = *(const uint4*)&g_Wolo[src];
        }
        __syncthreads();

#pragma unroll
        for (int ks = 0; ks < 4; ks++) {
            uint32_t ahi[4], alo[4];
            ldsm_x4(ahi, aaddr_hi0 + ks*32);
            ldsm_x4(alo, aaddr_lo0 + ks*32);
            const uint32_t bk_off = ks * 16 * XPAD * 2;
#pragma unroll
            for (int nt = 0; nt < 4; nt++) {
                uint32_t bhi[4], blo[4];
                ldsm_x4_t(bhi, baddr_hi0 + bk_off + nt*32);
                ldsm_x4_t(blo, baddr_lo0 + bk_off + nt*32);
                mma16816(c[nt*2],     ahi, bhi[0], bhi[1]);
                mma16816(c[nt*2 + 1], ahi, bhi[2], bhi[3]);
                mma16816(c[nt*2],     ahi, blo[0], blo[1]);
                mma16816(c[nt*2 + 1], ahi, blo[2], blo[3]);
                mma16816(c[nt*2],     alo, bhi[0], bhi[1]);
                mma16816(c[nt*2 + 1], alo, bhi[2], bhi[3]);
            }
        }
    }

    const int g  = lane >> 2;
    const int tc = (lane & 3) * 2;
    const int mr0 = m0 + w*16 + g;
    const int mr1 = mr0 + 8;
#pragma unroll
    for (int nt = 0; nt < 8; nt++) {
        int col = nt*8 + tc;
        float b0v = bo[n0 + col], b1v = bo[n0 + col + 1];
        *(float2*)(out + (size_t)mr0*ND + n0 + col) =
            make_float2(c[nt][0] + b0v, c[nt][1] + b1v);
        *(float2*)(out + (size_t)mr1*ND + n0 + col) =
            make_float2(c[nt][2] + b0v, c[nt][3] + b1v);
    }
}

// ---------------------------------------------------------------------------
extern "C" void kernel_launch(void* const* d_in, const int* in_sizes, int n_in,
                              void* d_out, int out_size)
{
    (void)in_sizes; (void)n_in; (void)out_size;
    const float* X  = (const float*)d_in[0];
    const float* Wq = (const float*)d_in[1];
    const float* Wk = (const float*)d_in[2];
    const float* Wv = (const float*)d_in[3];
    const float* Wo = (const float*)d_in[4];
    const float* bq = (const float*)d_in[5];
    const float* bk = (const float*)d_in[6];
    const float* bv = (const float*)d_in[7];
    const float* bo = (const float*)d_in[8];
    float* out = (float*)d_out;

    static int configured = 0;
    if (!configured) {
        cudaFuncSetAttribute(qkv_mma_kernel,
                             cudaFuncAttributeMaxDynamicSharedMemorySize, QKV_SMEM);
        cudaFuncSetAttribute(attn_kernel,
                             cudaFuncAttributeMaxDynamicSharedMemorySize, ATTN_SMEM);
        cudaFuncSetAttribute(oproj_mma_kernel,
                             cudaFuncAttributeMaxDynamicSharedMemorySize, QKV_SMEM);
        configured = 1;
    }

    split_x_kernel<<<NB*NT*ND/1024, 256>>>(X);
    split_w_kernel<<<dim3(NH*ND*DH/1024, 3), 256>>>(Wq, Wk, Wv);
    split_wo_kernel<<<NH*DH*ND/1024, 256>>>(Wo);
    qkv_mma_kernel<<<dim3(32, 16, 3), 256, QKV_SMEM>>>(bq, bk, bv);
    attn_kernel<<<dim3(32, 16, 2), 128, ATTN_SMEM>>>();
    oproj_mma_kernel<<<dim3(32, 16), 256, QKV_SMEM>>>(bo, out);
}